// round 1
// baseline (speedup 1.0000x reference)
#include <cuda_runtime.h>
#include <cstdint>

#define N_NODES 100000
#define F_IN    512
#define F_HID   256
#define F_OUT   40

// ---------------- scratch (device globals; no allocation allowed) ----------
__device__ __align__(128) float g_support1[(size_t)N_NODES * F_HID];   // 102.4 MB
__device__ __align__(128) float g_h1[(size_t)N_NODES * F_HID];         // 102.4 MB
__device__ __align__(128) float g_support2[(size_t)N_NODES * F_OUT];   // 16 MB
__device__ __align__(128) float g_h2[(size_t)N_NODES * F_OUT];         // 16 MB

// vectorized f32 atomic add (sm_90+), quarters RED op count
__device__ __forceinline__ void red_add_v4(float* addr, float a, float b, float c, float d) {
    asm volatile("red.global.add.v4.f32 [%0], {%1, %2, %3, %4};"
                 :: "l"(addr), "f"(a), "f"(b), "f"(c), "f"(d) : "memory");
}

// ---------------- SGEMM: C[M,N] = A[M,K] @ B[K,N], fp32, 64x64x16 tiles ----
#define BM 64
#define BN 64
#define BK 16
__global__ __launch_bounds__(256) void sgemm64(const float* __restrict__ A,
                                               const float* __restrict__ B,
                                               float* __restrict__ C,
                                               int M, int N, int K) {
    __shared__ float As[BK][BM];   // A stored transposed: As[k][m]
    __shared__ float Bs[BK][BN];

    const int tid = threadIdx.x;
    const int tx = tid & 15;          // 0..15 -> N micro
    const int ty = tid >> 4;          // 0..15 -> M micro
    const int rowBase = blockIdx.y * BM;
    const int colBase = blockIdx.x * BN;

    // A load map: thread -> (row = tid/4, k4 = (tid&3)*4), one float4 each
    const int ar  = tid >> 2;
    const int ak4 = (tid & 3) * 4;
    // B load map: thread -> (k = tid/16, c4 = (tid&15)*4), one float4 each
    const int bk  = tid >> 4;
    const int bc4 = (tid & 15) * 4;

    float acc[4][4];
    #pragma unroll
    for (int m = 0; m < 4; m++)
        #pragma unroll
        for (int n = 0; n < 4; n++) acc[m][n] = 0.f;

    for (int k0 = 0; k0 < K; k0 += BK) {
        // load A tile (guard M edge), store transposed into smem
        float4 av = make_float4(0.f, 0.f, 0.f, 0.f);
        const int arow = rowBase + ar;
        if (arow < M)
            av = *(const float4*)(A + (size_t)arow * K + k0 + ak4);
        As[ak4 + 0][ar] = av.x;
        As[ak4 + 1][ar] = av.y;
        As[ak4 + 2][ar] = av.z;
        As[ak4 + 3][ar] = av.w;

        // load B tile (K,N divisible by tile dims for our shapes)
        float4 bv = *(const float4*)(B + (size_t)(k0 + bk) * N + colBase + bc4);
        *(float4*)&Bs[bk][bc4] = bv;

        __syncthreads();

        #pragma unroll
        for (int k = 0; k < BK; k++) {
            const float4 a4 = *(const float4*)(&As[k][ty * 4]);
            const float4 b4 = *(const float4*)(&Bs[k][tx * 4]);
            const float am[4] = {a4.x, a4.y, a4.z, a4.w};
            const float bn[4] = {b4.x, b4.y, b4.z, b4.w};
            #pragma unroll
            for (int m = 0; m < 4; m++)
                #pragma unroll
                for (int n = 0; n < 4; n++)
                    acc[m][n] = fmaf(am[m], bn[n], acc[m][n]);
        }
        __syncthreads();
    }

    #pragma unroll
    for (int m = 0; m < 4; m++) {
        const int row = rowBase + ty * 4 + m;
        if (row < M) {
            float4 o = make_float4(acc[m][0], acc[m][1], acc[m][2], acc[m][3]);
            *(float4*)(C + (size_t)row * N + colBase + tx * 4) = o;
        }
    }
}

// ---------------- init accumulator with broadcast bias ---------------------
__global__ void init_bias(float* __restrict__ h, const float* __restrict__ b,
                          int total4, int cols4) {
    int t = blockIdx.x * blockDim.x + threadIdx.x;
    if (t < total4) {
        ((float4*)h)[t] = ((const float4*)b)[t % cols4];
    }
}

// ---------------- layer-1 scatter: one warp per edge, 256 feats ------------
__global__ __launch_bounds__(256) void scatter1(const int* __restrict__ src,
                                                const int* __restrict__ dst,
                                                const float* __restrict__ ew,
                                                int E) {
    const int w = (blockIdx.x * blockDim.x + threadIdx.x) >> 5;
    const int lane = threadIdx.x & 31;
    if (w >= E) return;
    const int s = src[w];
    const int d = dst[w];
    const float wt = ew[w];
    const float4* sp = (const float4*)(g_support1 + (size_t)s * F_HID);
    float* dp = g_h1 + (size_t)d * F_HID;
    #pragma unroll
    for (int i = 0; i < 2; i++) {
        const int j = lane + i * 32;       // float4 index 0..63
        const float4 v = __ldg(&sp[j]);
        red_add_v4(dp + j * 4, v.x * wt, v.y * wt, v.z * wt, v.w * wt);
    }
}

// ---------------- gemm2: support2 = relu(h1) @ W2, W2 in smem --------------
__global__ __launch_bounds__(256) void gemm2_relu(const float* __restrict__ W2) {
    __shared__ float W2s[F_HID * F_OUT];   // 40 KB
    for (int i = threadIdx.x; i < (F_HID * F_OUT) / 4; i += 256)
        ((float4*)W2s)[i] = ((const float4*)W2)[i];
    __syncthreads();

    const int n = blockIdx.x * blockDim.x + threadIdx.x;
    if (n >= N_NODES) return;

    float4 acc[F_OUT / 4];
    #pragma unroll
    for (int j = 0; j < F_OUT / 4; j++) acc[j] = make_float4(0.f, 0.f, 0.f, 0.f);

    const float4* hrow = (const float4*)(g_h1 + (size_t)n * F_HID);
    for (int k4 = 0; k4 < F_HID / 4; k4++) {
        const float4 h = __ldg(&hrow[k4]);
        const float hv[4] = {fmaxf(h.x, 0.f), fmaxf(h.y, 0.f),
                             fmaxf(h.z, 0.f), fmaxf(h.w, 0.f)};
        #pragma unroll
        for (int s = 0; s < 4; s++) {
            const float a = hv[s];
            const float4* wrow = (const float4*)(W2s + (k4 * 4 + s) * F_OUT);
            #pragma unroll
            for (int j = 0; j < F_OUT / 4; j++) {
                const float4 wv = wrow[j];
                acc[j].x = fmaf(a, wv.x, acc[j].x);
                acc[j].y = fmaf(a, wv.y, acc[j].y);
                acc[j].z = fmaf(a, wv.z, acc[j].z);
                acc[j].w = fmaf(a, wv.w, acc[j].w);
            }
        }
    }
    float4* orow = (float4*)(g_support2 + (size_t)n * F_OUT);
    #pragma unroll
    for (int j = 0; j < F_OUT / 4; j++) orow[j] = acc[j];
}

// ---------------- layer-2 scatter: 16 lanes per edge (10 active) -----------
__global__ __launch_bounds__(256) void scatter2(const int* __restrict__ src,
                                                const int* __restrict__ dst,
                                                const float* __restrict__ ew,
                                                int E) {
    const int t = blockIdx.x * blockDim.x + threadIdx.x;
    const int e = t >> 4;
    const int j4 = t & 15;
    if (e >= E || j4 >= F_OUT / 4) return;
    const int s = src[e];
    const int d = dst[e];
    const float wt = ew[e];
    const float4 v = __ldg((const float4*)(g_support2 + (size_t)s * F_OUT) + j4);
    red_add_v4(g_h2 + (size_t)d * F_OUT + j4 * 4,
               v.x * wt, v.y * wt, v.z * wt, v.w * wt);
}

// ---------------- log_softmax over 40 classes, one warp per row ------------
__global__ __launch_bounds__(256) void logsoftmax40(float* __restrict__ out) {
    const int row = (blockIdx.x * blockDim.x + threadIdx.x) >> 5;
    const int lane = threadIdx.x & 31;
    if (row >= N_NODES) return;
    const float* p = g_h2 + (size_t)row * F_OUT;
    const float NEG_INF = __int_as_float(0xff800000);
    const float v0 = p[lane];                                    // lane < 32 < 40 always valid
    const bool hi = (lane + 32) < F_OUT;
    const float v1 = hi ? p[lane + 32] : NEG_INF;
    float m = fmaxf(v0, v1);
    #pragma unroll
    for (int o = 16; o > 0; o >>= 1)
        m = fmaxf(m, __shfl_xor_sync(0xffffffffu, m, o));
    float s = expf(v0 - m) + (hi ? expf(v1 - m) : 0.f);
    #pragma unroll
    for (int o = 16; o > 0; o >>= 1)
        s += __shfl_xor_sync(0xffffffffu, s, o);
    const float l = m + logf(s);
    float* q = out + (size_t)row * F_OUT;
    q[lane] = v0 - l;
    if (hi) q[lane + 32] = v1 - l;
}

// ---------------- launch ----------------------------------------------------
extern "C" void kernel_launch(void* const* d_in, const int* in_sizes, int n_in,
                              void* d_out, int out_size) {
    const float* x   = (const float*)d_in[0];
    const int*   ei  = (const int*)d_in[1];
    const float* ew  = (const float*)d_in[2];
    const float* W1  = (const float*)d_in[3];
    const float* b1  = (const float*)d_in[4];
    const float* W2  = (const float*)d_in[5];
    const float* b2  = (const float*)d_in[6];
    float* out = (float*)d_out;

    const int E = in_sizes[2];
    const int* src = ei;
    const int* dst = ei + E;

    // support1 = x @ W1
    {
        dim3 grid(F_HID / BN, (N_NODES + BM - 1) / BM);
        float* s1;
        cudaGetSymbolAddress((void**)&s1, g_support1);
        sgemm64<<<grid, 256>>>(x, W1, s1, N_NODES, F_HID, F_IN);
    }
    // h1 = b1 (broadcast)
    {
        float* h1;
        cudaGetSymbolAddress((void**)&h1, g_h1);
        const int total4 = N_NODES * (F_HID / 4);
        init_bias<<<(total4 + 255) / 256, 256>>>(h1, b1, total4, F_HID / 4);
    }
    // h1 += scatter(ew * support1[src])
    {
        const long long threads = (long long)E * 32;
        scatter1<<<(unsigned)((threads + 255) / 256), 256>>>(src, dst, ew, E);
    }
    // support2 = relu(h1) @ W2
    gemm2_relu<<<(N_NODES + 255) / 256, 256>>>(W2);
    // h2 = b2 (broadcast)
    {
        float* h2;
        cudaGetSymbolAddress((void**)&h2, g_h2);
        const int total4 = N_NODES * (F_OUT / 4);
        init_bias<<<(total4 + 255) / 256, 256>>>(h2, b2, total4, F_OUT / 4);
    }
    // h2 += scatter(ew * support2[src])
    {
        const long long threads = (long long)E * 16;
        scatter2<<<(unsigned)((threads + 255) / 256), 256>>>(src, dst, ew, E);
    }
    // out = log_softmax(h2)
    logsoftmax40<<<(N_NODES * 32 + 255) / 256, 256>>>(out);
}

// round 2
// speedup vs baseline: 1.1943x; 1.1943x over previous
#include <cuda_runtime.h>
#include <cstdint>

#define N_NODES 100000
#define F_IN    512
#define F_HID   256
#define F_OUT   40

// ---------------- scratch (device globals; no allocation allowed) ----------
__device__ __align__(128) float g_support1[(size_t)N_NODES * F_HID];   // 102.4 MB
__device__ __align__(128) float g_h1[(size_t)N_NODES * F_HID];         // 102.4 MB
__device__ __align__(128) float g_support2[(size_t)N_NODES * F_OUT];   // 16 MB
__device__ __align__(128) float g_h2[(size_t)N_NODES * F_OUT];         // 16 MB

// vectorized f32 atomic add (sm_90+)
__device__ __forceinline__ void red_add_v4(float* addr, float a, float b, float c, float d) {
    asm volatile("red.global.add.v4.f32 [%0], {%1, %2, %3, %4};"
                 :: "l"(addr), "f"(a), "f"(b), "f"(c), "f"(d) : "memory");
}

__device__ __forceinline__ uint32_t f2tf32(float f) {
    uint32_t r;
    asm("cvt.rna.tf32.f32 %0, %1;" : "=r"(r) : "f"(f));
    return r;
}

__device__ __forceinline__ void mma_tf32(float* c, const uint32_t* a, const uint32_t* b) {
    asm volatile("mma.sync.aligned.m16n8k8.row.col.f32.tf32.tf32.f32 "
                 "{%0,%1,%2,%3}, {%4,%5,%6,%7}, {%8,%9}, {%0,%1,%2,%3};"
                 : "+f"(c[0]), "+f"(c[1]), "+f"(c[2]), "+f"(c[3])
                 : "r"(a[0]), "r"(a[1]), "r"(a[2]), "r"(a[3]),
                   "r"(b[0]), "r"(b[1]));
}

// ================= gemm1: support1 = x @ W1  (TF32 tensor cores) ===========
// M=100000, K=512, N=256.  Block tile 128x128x16, 256 threads = 8 warps,
// warp tile 64x32 (2 warps along M, 4 along N), 16 mma per warp per k8.
// Smem holds fragments in mma register order so compute does clean
// LDS.128 (A) / LDS.64 (B) per fragment.
#define G1_BM 128
#define G1_BK 16

__global__ __launch_bounds__(256) void gemm1_tf32(const float* __restrict__ A,
                                                  const float* __restrict__ B,
                                                  float* __restrict__ C,
                                                  int M) {
    // [buf][ks][mt][lane][reg]
    __shared__ uint32_t As[2][2][8][32][4];   // 16 KB
    __shared__ uint32_t Bs[2][2][16][32][2];  // 16 KB

    const int tid  = threadIdx.x;
    const int lane = tid & 31;
    const int warp = tid >> 5;
    const int wm = warp & 1;     // 0..1 -> 64-row slab
    const int wn = warp >> 1;    // 0..3 -> 32-col slab
    const int rowBase = blockIdx.y * G1_BM;
    const int colBase = blockIdx.x * 128;

    // A fill: row = tid/2; two float4 at k-offsets (tid&1)*8 and +4
    const int ar = tid >> 1;
    const int af = (tid & 1) * 2;          // float4 index base within row (0 or 2)
    // B fill: k row = tid/16; two float4 at col offsets
    const int bk  = tid >> 4;
    const int bn4 = (tid & 15) * 2;        // float4 index base within 128 cols

    float acc[4][4][4];
    #pragma unroll
    for (int mt = 0; mt < 4; mt++)
        #pragma unroll
        for (int nt = 0; nt < 4; nt++)
            #pragma unroll
            for (int r = 0; r < 4; r++) acc[mt][nt][r] = 0.f;

    float4 pa[2], pb[2];

    const int arow = rowBase + ar;
    const float* Arow = A + (size_t)arow * F_IN;

    // ---- prologue: load tile 0 ----
    {
        pa[0] = make_float4(0.f, 0.f, 0.f, 0.f);
        pa[1] = pa[0];
        if (arow < M) {
            pa[0] = *(const float4*)(Arow + (af + 0) * 4);
            pa[1] = *(const float4*)(Arow + (af + 1) * 4);
        }
        pb[0] = *(const float4*)(B + (size_t)bk * F_HID + colBase + (bn4 + 0) * 4);
        pb[1] = *(const float4*)(B + (size_t)bk * F_HID + colBase + (bn4 + 1) * 4);
    }
    // store tile 0 into buffer 0
    {
        const int rr = ar & 15, mt = ar >> 4;
        #pragma unroll
        for (int j = 0; j < 2; j++) {
            const int kloc = (af + j) * 4;
            const int ks = kloc >> 3;
            const int regb = (rr >> 3) + 2 * ((kloc & 7) >> 2);
            const int l0 = (rr & 7) * 4;
            As[0][ks][mt][l0 + 0][regb] = f2tf32(pa[j].x);
            As[0][ks][mt][l0 + 1][regb] = f2tf32(pa[j].y);
            As[0][ks][mt][l0 + 2][regb] = f2tf32(pa[j].z);
            As[0][ks][mt][l0 + 3][regb] = f2tf32(pa[j].w);
        }
        const int ksb = bk >> 3, kk3 = bk & 3, regB = (bk >> 2) & 1;
        #pragma unroll
        for (int j = 0; j < 2; j++) {
            const int nloc = (bn4 + j) * 4;
            const int nt = nloc >> 3, nn = nloc & 7;
            Bs[0][ksb][nt][(nn + 0) * 4 + kk3][regB] = f2tf32(pb[j].x);
            Bs[0][ksb][nt][(nn + 1) * 4 + kk3][regB] = f2tf32(pb[j].y);
            Bs[0][ksb][nt][(nn + 2) * 4 + kk3][regB] = f2tf32(pb[j].z);
            Bs[0][ksb][nt][(nn + 3) * 4 + kk3][regB] = f2tf32(pb[j].w);
        }
    }
    __syncthreads();

    const int NT = F_IN / G1_BK;   // 32 tiles
    for (int t = 0; t < NT; t++) {
        const int buf = t & 1;
        // issue next tile's global loads early
        if (t + 1 < NT) {
            const int k0 = (t + 1) * G1_BK;
            pa[0] = make_float4(0.f, 0.f, 0.f, 0.f);
            pa[1] = pa[0];
            if (arow < M) {
                pa[0] = *(const float4*)(Arow + k0 + (af + 0) * 4);
                pa[1] = *(const float4*)(Arow + k0 + (af + 1) * 4);
            }
            pb[0] = *(const float4*)(B + (size_t)(k0 + bk) * F_HID + colBase + (bn4 + 0) * 4);
            pb[1] = *(const float4*)(B + (size_t)(k0 + bk) * F_HID + colBase + (bn4 + 1) * 4);
        }
        // compute from smem
        #pragma unroll
        for (int ks = 0; ks < 2; ks++) {
            uint32_t afr[4][4];
            uint32_t bfr[4][2];
            #pragma unroll
            for (int mt = 0; mt < 4; mt++) {
                uint4 v = *(const uint4*)&As[buf][ks][wm * 4 + mt][lane][0];
                afr[mt][0] = v.x; afr[mt][1] = v.y; afr[mt][2] = v.z; afr[mt][3] = v.w;
            }
            #pragma unroll
            for (int nt = 0; nt < 4; nt++) {
                uint2 v = *(const uint2*)&Bs[buf][ks][wn * 4 + nt][lane][0];
                bfr[nt][0] = v.x; bfr[nt][1] = v.y;
            }
            #pragma unroll
            for (int mt = 0; mt < 4; mt++)
                #pragma unroll
                for (int nt = 0; nt < 4; nt++)
                    mma_tf32(acc[mt][nt], afr[mt], bfr[nt]);
        }
        // stash next tile into other buffer
        if (t + 1 < NT) {
            const int nb = buf ^ 1;
            const int rr = ar & 15, mt = ar >> 4;
            #pragma unroll
            for (int j = 0; j < 2; j++) {
                const int kloc = (af + j) * 4;
                const int ks = kloc >> 3;
                const int regb = (rr >> 3) + 2 * ((kloc & 7) >> 2);
                const int l0 = (rr & 7) * 4;
                As[nb][ks][mt][l0 + 0][regb] = f2tf32(pa[j].x);
                As[nb][ks][mt][l0 + 1][regb] = f2tf32(pa[j].y);
                As[nb][ks][mt][l0 + 2][regb] = f2tf32(pa[j].z);
                As[nb][ks][mt][l0 + 3][regb] = f2tf32(pa[j].w);
            }
            const int ksb = bk >> 3, kk3 = bk & 3, regB = (bk >> 2) & 1;
            #pragma unroll
            for (int j = 0; j < 2; j++) {
                const int nloc = (bn4 + j) * 4;
                const int nt = nloc >> 3, nn = nloc & 7;
                Bs[nb][ksb][nt][(nn + 0) * 4 + kk3][regB] = f2tf32(pb[j].x);
                Bs[nb][ksb][nt][(nn + 1) * 4 + kk3][regB] = f2tf32(pb[j].y);
                Bs[nb][ksb][nt][(nn + 2) * 4 + kk3][regB] = f2tf32(pb[j].z);
                Bs[nb][ksb][nt][(nn + 3) * 4 + kk3][regB] = f2tf32(pb[j].w);
            }
        }
        __syncthreads();
    }

    // ---- epilogue: write C ----
    #pragma unroll
    for (int mt = 0; mt < 4; mt++) {
        const int row0 = rowBase + wm * 64 + mt * 16 + (lane >> 2);
        #pragma unroll
        for (int nt = 0; nt < 4; nt++) {
            const int col = colBase + wn * 32 + nt * 8 + (lane & 3) * 2;
            if (row0 < M)
                *(float2*)(C + (size_t)row0 * F_HID + col) =
                    make_float2(acc[mt][nt][0], acc[mt][nt][1]);
            if (row0 + 8 < M)
                *(float2*)(C + (size_t)(row0 + 8) * F_HID + col) =
                    make_float2(acc[mt][nt][2], acc[mt][nt][3]);
        }
    }
}

// ---------------- init h1 chunk (128 features) with bias -------------------
__global__ void init_h1_chunk(const float* __restrict__ b1, int off) {
    const int t = blockIdx.x * blockDim.x + threadIdx.x;
    if (t >= N_NODES * 32) return;
    const int n = t >> 5, j = t & 31;
    ((float4*)(g_h1 + (size_t)n * F_HID + off))[j] = ((const float4*)(b1 + off))[j];
}

// ---------------- layer-1 scatter: one warp per edge, 128-feature chunk ----
// Chunking keeps (support1 chunk + h1 chunk) = 102 MB inside L2, so the
// degree-32 gather reuse turns into L2 hits instead of HBM traffic.
__global__ __launch_bounds__(256) void scatter1_chunk(const int* __restrict__ src,
                                                      const int* __restrict__ dst,
                                                      const float* __restrict__ ew,
                                                      int E, int off) {
    const int w = (blockIdx.x * blockDim.x + threadIdx.x) >> 5;
    const int lane = threadIdx.x & 31;
    if (w >= E) return;
    const int s = src[w];
    const int d = dst[w];
    const float wt = ew[w];
    const float4 v = __ldg((const float4*)(g_support1 + (size_t)s * F_HID + off) + lane);
    red_add_v4(g_h1 + (size_t)d * F_HID + off + lane * 4,
               v.x * wt, v.y * wt, v.z * wt, v.w * wt);
}

// ---------------- gemm2: support2 = relu(h1) @ W2, 2 nodes per thread ------
__global__ __launch_bounds__(256) void gemm2_relu(const float* __restrict__ W2) {
    __shared__ float W2s[F_HID * F_OUT];   // 40 KB
    for (int i = threadIdx.x; i < (F_HID * F_OUT) / 4; i += 256)
        ((float4*)W2s)[i] = ((const float4*)W2)[i];
    __syncthreads();

    const int HALF = N_NODES / 2;
    const int n = blockIdx.x * blockDim.x + threadIdx.x;
    if (n >= HALF) return;

    float4 acc0[F_OUT / 4], acc1[F_OUT / 4];
    #pragma unroll
    for (int j = 0; j < F_OUT / 4; j++) {
        acc0[j] = make_float4(0.f, 0.f, 0.f, 0.f);
        acc1[j] = acc0[j];
    }

    const float4* hr0 = (const float4*)(g_h1 + (size_t)n * F_HID);
    const float4* hr1 = (const float4*)(g_h1 + (size_t)(n + HALF) * F_HID);
    for (int k4 = 0; k4 < F_HID / 4; k4++) {
        const float4 ha = __ldg(&hr0[k4]);
        const float4 hb = __ldg(&hr1[k4]);
        const float av[4] = {fmaxf(ha.x, 0.f), fmaxf(ha.y, 0.f),
                             fmaxf(ha.z, 0.f), fmaxf(ha.w, 0.f)};
        const float bv[4] = {fmaxf(hb.x, 0.f), fmaxf(hb.y, 0.f),
                             fmaxf(hb.z, 0.f), fmaxf(hb.w, 0.f)};
        #pragma unroll
        for (int s = 0; s < 4; s++) {
            const float a = av[s], b = bv[s];
            const float4* wrow = (const float4*)(W2s + (k4 * 4 + s) * F_OUT);
            #pragma unroll
            for (int j = 0; j < F_OUT / 4; j++) {
                const float4 wv = wrow[j];
                acc0[j].x = fmaf(a, wv.x, acc0[j].x);
                acc0[j].y = fmaf(a, wv.y, acc0[j].y);
                acc0[j].z = fmaf(a, wv.z, acc0[j].z);
                acc0[j].w = fmaf(a, wv.w, acc0[j].w);
                acc1[j].x = fmaf(b, wv.x, acc1[j].x);
                acc1[j].y = fmaf(b, wv.y, acc1[j].y);
                acc1[j].z = fmaf(b, wv.z, acc1[j].z);
                acc1[j].w = fmaf(b, wv.w, acc1[j].w);
            }
        }
    }
    float4* o0 = (float4*)(g_support2 + (size_t)n * F_OUT);
    float4* o1 = (float4*)(g_support2 + (size_t)(n + HALF) * F_OUT);
    #pragma unroll
    for (int j = 0; j < F_OUT / 4; j++) { o0[j] = acc0[j]; o1[j] = acc1[j]; }
}

// ---------------- init h2 with bias ----------------------------------------
__global__ void init_bias(float* __restrict__ h, const float* __restrict__ b,
                          int total4, int cols4) {
    int t = blockIdx.x * blockDim.x + threadIdx.x;
    if (t < total4) {
        ((float4*)h)[t] = ((const float4*)b)[t % cols4];
    }
}

// ---------------- layer-2 scatter: 16 lanes per edge (10 active) -----------
__global__ __launch_bounds__(256) void scatter2(const int* __restrict__ src,
                                                const int* __restrict__ dst,
                                                const float* __restrict__ ew,
                                                int E) {
    const int t = blockIdx.x * blockDim.x + threadIdx.x;
    const int e = t >> 4;
    const int j4 = t & 15;
    if (e >= E || j4 >= F_OUT / 4) return;
    const int s = src[e];
    const int d = dst[e];
    const float wt = ew[e];
    const float4 v = __ldg((const float4*)(g_support2 + (size_t)s * F_OUT) + j4);
    red_add_v4(g_h2 + (size_t)d * F_OUT + j4 * 4,
               v.x * wt, v.y * wt, v.z * wt, v.w * wt);
}

// ---------------- log_softmax over 40 classes, one warp per row ------------
__global__ __launch_bounds__(256) void logsoftmax40(float* __restrict__ out) {
    const int row = (blockIdx.x * blockDim.x + threadIdx.x) >> 5;
    const int lane = threadIdx.x & 31;
    if (row >= N_NODES) return;
    const float* p = g_h2 + (size_t)row * F_OUT;
    const float NEG_INF = __int_as_float(0xff800000);
    const float v0 = p[lane];
    const bool hi = (lane + 32) < F_OUT;
    const float v1 = hi ? p[lane + 32] : NEG_INF;
    float m = fmaxf(v0, v1);
    #pragma unroll
    for (int o = 16; o > 0; o >>= 1)
        m = fmaxf(m, __shfl_xor_sync(0xffffffffu, m, o));
    float s = expf(v0 - m) + (hi ? expf(v1 - m) : 0.f);
    #pragma unroll
    for (int o = 16; o > 0; o >>= 1)
        s += __shfl_xor_sync(0xffffffffu, s, o);
    const float l = m + logf(s);
    float* q = out + (size_t)row * F_OUT;
    q[lane] = v0 - l;
    if (hi) q[lane + 32] = v1 - l;
}

// ---------------- launch ----------------------------------------------------
extern "C" void kernel_launch(void* const* d_in, const int* in_sizes, int n_in,
                              void* d_out, int out_size) {
    const float* x   = (const float*)d_in[0];
    const int*   ei  = (const int*)d_in[1];
    const float* ew  = (const float*)d_in[2];
    const float* W1  = (const float*)d_in[3];
    const float* b1  = (const float*)d_in[4];
    const float* W2  = (const float*)d_in[5];
    const float* b2  = (const float*)d_in[6];
    float* out = (float*)d_out;

    const int E = in_sizes[2];
    const int* src = ei;
    const int* dst = ei + E;

    // support1 = x @ W1  (TF32 mma)
    {
        float* s1;
        cudaGetSymbolAddress((void**)&s1, g_support1);
        dim3 grid(F_HID / 128, (N_NODES + G1_BM - 1) / G1_BM);
        gemm1_tf32<<<grid, 256>>>(x, W1, s1, N_NODES);
    }
    // layer-1 propagate, feature-chunked for L2 residency
    {
        const int initBlocks = (N_NODES * 32 + 255) / 256;
        const long long sthreads = (long long)E * 32;
        const unsigned sBlocks = (unsigned)((sthreads + 255) / 256);
        for (int c = 0; c < 2; c++) {
            const int off = c * 128;
            init_h1_chunk<<<initBlocks, 256>>>(b1, off);
            scatter1_chunk<<<sBlocks, 256>>>(src, dst, ew, E, off);
        }
    }
    // support2 = relu(h1) @ W2
    gemm2_relu<<<(N_NODES / 2 + 255) / 256, 256>>>(W2);
    // h2 = b2, then scatter
    {
        float* h2;
        cudaGetSymbolAddress((void**)&h2, g_h2);
        const int total4 = N_NODES * (F_OUT / 4);
        init_bias<<<(total4 + 255) / 256, 256>>>(h2, b2, total4, F_OUT / 4);
        const long long threads = (long long)E * 16;
        scatter2<<<(unsigned)((threads + 255) / 256), 256>>>(src, dst, ew, E);
    }
    // out = log_softmax(h2)
    logsoftmax40<<<(N_NODES * 32 + 255) / 256, 256>>>(out);
}

// round 3
// speedup vs baseline: 2.1150x; 1.7709x over previous
#include <cuda_runtime.h>
#include <cstdint>

#define N_NODES 100000
#define F_IN    512
#define F_HID   256
#define F_OUT   40
#define E_MAX   3200000

#define SCAN_B  512
#define SCAN_NB ((N_NODES + SCAN_B - 1) / SCAN_B)   // 196

// ---------------- scratch (device globals; no allocation allowed) ----------
__device__ __align__(128) float g_support1[(size_t)N_NODES * F_HID];   // 102.4 MB
__device__ __align__(128) float g_h1[(size_t)N_NODES * F_HID];         // 102.4 MB
__device__ __align__(128) float g_support2[(size_t)N_NODES * F_OUT];   // 16 MB

__device__ int  g_cnt[N_NODES];
__device__ int  g_off[N_NODES];
__device__ int  g_pos[N_NODES];
__device__ int  g_blksum[SCAN_NB];
__device__ __align__(16) int2 g_csr[E_MAX];    // (src, float-bits of w), 25.6 MB

// ---------------- TF32 mma helpers -----------------------------------------
__device__ __forceinline__ uint32_t f2tf32(float f) {
    uint32_t r;
    asm("cvt.rna.tf32.f32 %0, %1;" : "=r"(r) : "f"(f));
    return r;
}

__device__ __forceinline__ void mma_tf32(float* c, const uint32_t* a, const uint32_t* b) {
    asm volatile("mma.sync.aligned.m16n8k8.row.col.f32.tf32.tf32.f32 "
                 "{%0,%1,%2,%3}, {%4,%5,%6,%7}, {%8,%9}, {%0,%1,%2,%3};"
                 : "+f"(c[0]), "+f"(c[1]), "+f"(c[2]), "+f"(c[3])
                 : "r"(a[0]), "r"(a[1]), "r"(a[2]), "r"(a[3]),
                   "r"(b[0]), "r"(b[1]));
}

// ================= gemm1: support1 = x @ W1  (TF32 tensor cores) ===========
#define G1_BM 128
#define G1_BK 16

__global__ __launch_bounds__(256) void gemm1_tf32(const float* __restrict__ A,
                                                  const float* __restrict__ B,
                                                  float* __restrict__ C,
                                                  int M) {
    __shared__ uint32_t As[2][2][8][32][4];   // 16 KB
    __shared__ uint32_t Bs[2][2][16][32][2];  // 16 KB

    const int tid  = threadIdx.x;
    const int lane = tid & 31;
    const int warp = tid >> 5;
    const int wm = warp & 1;
    const int wn = warp >> 1;
    const int rowBase = blockIdx.y * G1_BM;
    const int colBase = blockIdx.x * 128;

    const int ar = tid >> 1;
    const int af = (tid & 1) * 2;
    const int bk  = tid >> 4;
    const int bn4 = (tid & 15) * 2;

    float acc[4][4][4];
    #pragma unroll
    for (int mt = 0; mt < 4; mt++)
        #pragma unroll
        for (int nt = 0; nt < 4; nt++)
            #pragma unroll
            for (int r = 0; r < 4; r++) acc[mt][nt][r] = 0.f;

    float4 pa[2], pb[2];
    const int arow = rowBase + ar;
    const float* Arow = A + (size_t)arow * F_IN;

    {
        pa[0] = make_float4(0.f, 0.f, 0.f, 0.f);
        pa[1] = pa[0];
        if (arow < M) {
            pa[0] = *(const float4*)(Arow + (af + 0) * 4);
            pa[1] = *(const float4*)(Arow + (af + 1) * 4);
        }
        pb[0] = *(const float4*)(B + (size_t)bk * F_HID + colBase + (bn4 + 0) * 4);
        pb[1] = *(const float4*)(B + (size_t)bk * F_HID + colBase + (bn4 + 1) * 4);
    }
    {
        const int rr = ar & 15, mt = ar >> 4;
        #pragma unroll
        for (int j = 0; j < 2; j++) {
            const int kloc = (af + j) * 4;
            const int ks = kloc >> 3;
            const int regb = (rr >> 3) + 2 * ((kloc & 7) >> 2);
            const int l0 = (rr & 7) * 4;
            As[0][ks][mt][l0 + 0][regb] = f2tf32(pa[j].x);
            As[0][ks][mt][l0 + 1][regb] = f2tf32(pa[j].y);
            As[0][ks][mt][l0 + 2][regb] = f2tf32(pa[j].z);
            As[0][ks][mt][l0 + 3][regb] = f2tf32(pa[j].w);
        }
        const int ksb = bk >> 3, kk3 = bk & 3, regB = (bk >> 2) & 1;
        #pragma unroll
        for (int j = 0; j < 2; j++) {
            const int nloc = (bn4 + j) * 4;
            const int nt = nloc >> 3, nn = nloc & 7;
            Bs[0][ksb][nt][(nn + 0) * 4 + kk3][regB] = f2tf32(pb[j].x);
            Bs[0][ksb][nt][(nn + 1) * 4 + kk3][regB] = f2tf32(pb[j].y);
            Bs[0][ksb][nt][(nn + 2) * 4 + kk3][regB] = f2tf32(pb[j].z);
            Bs[0][ksb][nt][(nn + 3) * 4 + kk3][regB] = f2tf32(pb[j].w);
        }
    }
    __syncthreads();

    const int NT = F_IN / G1_BK;
    for (int t = 0; t < NT; t++) {
        const int buf = t & 1;
        if (t + 1 < NT) {
            const int k0 = (t + 1) * G1_BK;
            pa[0] = make_float4(0.f, 0.f, 0.f, 0.f);
            pa[1] = pa[0];
            if (arow < M) {
                pa[0] = *(const float4*)(Arow + k0 + (af + 0) * 4);
                pa[1] = *(const float4*)(Arow + k0 + (af + 1) * 4);
            }
            pb[0] = *(const float4*)(B + (size_t)(k0 + bk) * F_HID + colBase + (bn4 + 0) * 4);
            pb[1] = *(const float4*)(B + (size_t)(k0 + bk) * F_HID + colBase + (bn4 + 1) * 4);
        }
        #pragma unroll
        for (int ks = 0; ks < 2; ks++) {
            uint32_t afr[4][4];
            uint32_t bfr[4][2];
            #pragma unroll
            for (int mt = 0; mt < 4; mt++) {
                uint4 v = *(const uint4*)&As[buf][ks][wm * 4 + mt][lane][0];
                afr[mt][0] = v.x; afr[mt][1] = v.y; afr[mt][2] = v.z; afr[mt][3] = v.w;
            }
            #pragma unroll
            for (int nt = 0; nt < 4; nt++) {
                uint2 v = *(const uint2*)&Bs[buf][ks][wn * 4 + nt][lane][0];
                bfr[nt][0] = v.x; bfr[nt][1] = v.y;
            }
            #pragma unroll
            for (int mt = 0; mt < 4; mt++)
                #pragma unroll
                for (int nt = 0; nt < 4; nt++)
                    mma_tf32(acc[mt][nt], afr[mt], bfr[nt]);
        }
        if (t + 1 < NT) {
            const int nb = buf ^ 1;
            const int rr = ar & 15, mt = ar >> 4;
            #pragma unroll
            for (int j = 0; j < 2; j++) {
                const int kloc = (af + j) * 4;
                const int ks = kloc >> 3;
                const int regb = (rr >> 3) + 2 * ((kloc & 7) >> 2);
                const int l0 = (rr & 7) * 4;
                As[nb][ks][mt][l0 + 0][regb] = f2tf32(pa[j].x);
                As[nb][ks][mt][l0 + 1][regb] = f2tf32(pa[j].y);
                As[nb][ks][mt][l0 + 2][regb] = f2tf32(pa[j].z);
                As[nb][ks][mt][l0 + 3][regb] = f2tf32(pa[j].w);
            }
            const int ksb = bk >> 3, kk3 = bk & 3, regB = (bk >> 2) & 1;
            #pragma unroll
            for (int j = 0; j < 2; j++) {
                const int nloc = (bn4 + j) * 4;
                const int nt = nloc >> 3, nn = nloc & 7;
                Bs[nb][ksb][nt][(nn + 0) * 4 + kk3][regB] = f2tf32(pb[j].x);
                Bs[nb][ksb][nt][(nn + 1) * 4 + kk3][regB] = f2tf32(pb[j].y);
                Bs[nb][ksb][nt][(nn + 2) * 4 + kk3][regB] = f2tf32(pb[j].z);
                Bs[nb][ksb][nt][(nn + 3) * 4 + kk3][regB] = f2tf32(pb[j].w);
            }
        }
        __syncthreads();
    }

    #pragma unroll
    for (int mt = 0; mt < 4; mt++) {
        const int row0 = rowBase + wm * 64 + mt * 16 + (lane >> 2);
        #pragma unroll
        for (int nt = 0; nt < 4; nt++) {
            const int col = colBase + wn * 32 + nt * 8 + (lane & 3) * 2;
            if (row0 < M)
                *(float2*)(C + (size_t)row0 * F_HID + col) =
                    make_float2(acc[mt][nt][0], acc[mt][nt][1]);
            if (row0 + 8 < M)
                *(float2*)(C + (size_t)(row0 + 8) * F_HID + col) =
                    make_float2(acc[mt][nt][2], acc[mt][nt][3]);
        }
    }
}

// ================= CSR build =================================================
__global__ void zero_cnt() {
    const int i = blockIdx.x * blockDim.x + threadIdx.x;
    if (i < N_NODES) g_cnt[i] = 0;
}

__global__ void hist_dst(const int* __restrict__ dst, int E) {
    const int e = blockIdx.x * blockDim.x + threadIdx.x;
    if (e < E) atomicAdd(&g_cnt[dst[e]], 1);
}

__global__ void scan_block() {
    __shared__ int sh[SCAN_B];
    const int t = threadIdx.x;
    const int i = blockIdx.x * SCAN_B + t;
    const int v = (i < N_NODES) ? g_cnt[i] : 0;
    sh[t] = v;
    __syncthreads();
    #pragma unroll
    for (int o = 1; o < SCAN_B; o <<= 1) {
        int x = 0;
        if (t >= o) x = sh[t - o];
        __syncthreads();
        sh[t] += x;
        __syncthreads();
    }
    if (i < N_NODES) g_off[i] = sh[t] - v;      // exclusive within block
    if (t == SCAN_B - 1) g_blksum[blockIdx.x] = sh[t];
}

__global__ void scan_top() {
    __shared__ int sh[256];
    const int t = threadIdx.x;
    const int v = (t < SCAN_NB) ? g_blksum[t] : 0;
    sh[t] = v;
    __syncthreads();
    #pragma unroll
    for (int o = 1; o < 256; o <<= 1) {
        int x = 0;
        if (t >= o) x = sh[t - o];
        __syncthreads();
        sh[t] += x;
        __syncthreads();
    }
    if (t < SCAN_NB) g_blksum[t] = sh[t] - v;   // exclusive
}

__global__ void scan_add() {
    const int i = blockIdx.x * blockDim.x + threadIdx.x;
    if (i < N_NODES) {
        const int o = g_off[i] + g_blksum[i / SCAN_B];
        g_off[i] = o;
        g_pos[i] = o;
    }
}

__global__ void fill_csr(const int* __restrict__ src, const int* __restrict__ dst,
                         const float* __restrict__ ew, int E) {
    const int e = blockIdx.x * blockDim.x + threadIdx.x;
    if (e < E) {
        const int p = atomicAdd(&g_pos[dst[e]], 1);
        g_csr[p] = make_int2(src[e], __float_as_int(ew[e]));
    }
}

// ================= layer-1 gather: warp per node, 128-feat chunk =============
__global__ __launch_bounds__(256) void gather1(const float* __restrict__ b1, int off) {
    const int n = (blockIdx.x * blockDim.x + threadIdx.x) >> 5;
    const int lane = threadIdx.x & 31;
    if (n >= N_NODES) return;
    const int beg = g_off[n];
    const int end = beg + g_cnt[n];

    float4 acc = __ldg((const float4*)(b1 + off) + lane);

    int e = beg;
    for (; e + 1 < end; e += 2) {
        const int2 c0 = __ldg(&g_csr[e]);
        const int2 c1 = __ldg(&g_csr[e + 1]);
        const float w0 = __int_as_float(c0.y);
        const float w1 = __int_as_float(c1.y);
        const float4 v0 = __ldg((const float4*)(g_support1 + (size_t)c0.x * F_HID + off) + lane);
        const float4 v1 = __ldg((const float4*)(g_support1 + (size_t)c1.x * F_HID + off) + lane);
        acc.x = fmaf(w0, v0.x, acc.x); acc.y = fmaf(w0, v0.y, acc.y);
        acc.z = fmaf(w0, v0.z, acc.z); acc.w = fmaf(w0, v0.w, acc.w);
        acc.x = fmaf(w1, v1.x, acc.x); acc.y = fmaf(w1, v1.y, acc.y);
        acc.z = fmaf(w1, v1.z, acc.z); acc.w = fmaf(w1, v1.w, acc.w);
    }
    if (e < end) {
        const int2 c0 = __ldg(&g_csr[e]);
        const float w0 = __int_as_float(c0.y);
        const float4 v0 = __ldg((const float4*)(g_support1 + (size_t)c0.x * F_HID + off) + lane);
        acc.x = fmaf(w0, v0.x, acc.x); acc.y = fmaf(w0, v0.y, acc.y);
        acc.z = fmaf(w0, v0.z, acc.z); acc.w = fmaf(w0, v0.w, acc.w);
    }
    ((float4*)(g_h1 + (size_t)n * F_HID + off))[lane] = acc;
}

// ================= gemm2: support2 = relu(h1) @ W2 ==========================
__global__ __launch_bounds__(256) void gemm2_relu(const float* __restrict__ W2) {
    __shared__ float W2s[F_HID * F_OUT];   // 40 KB
    for (int i = threadIdx.x; i < (F_HID * F_OUT) / 4; i += 256)
        ((float4*)W2s)[i] = ((const float4*)W2)[i];
    __syncthreads();

    const int HALF = N_NODES / 2;
    const int n = blockIdx.x * blockDim.x + threadIdx.x;
    if (n >= HALF) return;

    float4 acc0[F_OUT / 4], acc1[F_OUT / 4];
    #pragma unroll
    for (int j = 0; j < F_OUT / 4; j++) {
        acc0[j] = make_float4(0.f, 0.f, 0.f, 0.f);
        acc1[j] = acc0[j];
    }

    const float4* hr0 = (const float4*)(g_h1 + (size_t)n * F_HID);
    const float4* hr1 = (const float4*)(g_h1 + (size_t)(n + HALF) * F_HID);
    for (int k4 = 0; k4 < F_HID / 4; k4++) {
        const float4 ha = __ldg(&hr0[k4]);
        const float4 hb = __ldg(&hr1[k4]);
        const float av[4] = {fmaxf(ha.x, 0.f), fmaxf(ha.y, 0.f),
                             fmaxf(ha.z, 0.f), fmaxf(ha.w, 0.f)};
        const float bv[4] = {fmaxf(hb.x, 0.f), fmaxf(hb.y, 0.f),
                             fmaxf(hb.z, 0.f), fmaxf(hb.w, 0.f)};
        #pragma unroll
        for (int s = 0; s < 4; s++) {
            const float a = av[s], b = bv[s];
            const float4* wrow = (const float4*)(W2s + (k4 * 4 + s) * F_OUT);
            #pragma unroll
            for (int j = 0; j < F_OUT / 4; j++) {
                const float4 wv = wrow[j];
                acc0[j].x = fmaf(a, wv.x, acc0[j].x);
                acc0[j].y = fmaf(a, wv.y, acc0[j].y);
                acc0[j].z = fmaf(a, wv.z, acc0[j].z);
                acc0[j].w = fmaf(a, wv.w, acc0[j].w);
                acc1[j].x = fmaf(b, wv.x, acc1[j].x);
                acc1[j].y = fmaf(b, wv.y, acc1[j].y);
                acc1[j].z = fmaf(b, wv.z, acc1[j].z);
                acc1[j].w = fmaf(b, wv.w, acc1[j].w);
            }
        }
    }
    float4* o0 = (float4*)(g_support2 + (size_t)n * F_OUT);
    float4* o1 = (float4*)(g_support2 + (size_t)(n + HALF) * F_OUT);
    #pragma unroll
    for (int j = 0; j < F_OUT / 4; j++) { o0[j] = acc0[j]; o1[j] = acc1[j]; }
}

// ========== layer-2 gather fused with log_softmax: warp per node ============
__global__ __launch_bounds__(256) void gather2_softmax(const float* __restrict__ b2,
                                                       float* __restrict__ out) {
    const int n = (blockIdx.x * blockDim.x + threadIdx.x) >> 5;
    const int lane = threadIdx.x & 31;
    if (n >= N_NODES) return;
    const int beg = g_off[n];
    const int end = beg + g_cnt[n];
    const bool hi = lane < (F_OUT - 32);   // lanes 0..7 also own feature 32+lane

    float accA = __ldg(b2 + lane);
    float accB = hi ? __ldg(b2 + 32 + lane) : 0.f;

    for (int e = beg; e < end; e++) {
        const int2 c = __ldg(&g_csr[e]);
        const float w = __int_as_float(c.y);
        const float* row = g_support2 + (size_t)c.x * F_OUT;
        accA = fmaf(w, __ldg(row + lane), accA);
        if (hi) accB = fmaf(w, __ldg(row + 32 + lane), accB);
    }

    const float NEG_INF = __int_as_float(0xff800000);
    float m = fmaxf(accA, hi ? accB : NEG_INF);
    #pragma unroll
    for (int o = 16; o > 0; o >>= 1)
        m = fmaxf(m, __shfl_xor_sync(0xffffffffu, m, o));
    float s = expf(accA - m) + (hi ? expf(accB - m) : 0.f);
    #pragma unroll
    for (int o = 16; o > 0; o >>= 1)
        s += __shfl_xor_sync(0xffffffffu, s, o);
    const float l = m + logf(s);

    float* q = out + (size_t)n * F_OUT;
    q[lane] = accA - l;
    if (hi) q[32 + lane] = accB - l;
}

// ---------------- launch ----------------------------------------------------
extern "C" void kernel_launch(void* const* d_in, const int* in_sizes, int n_in,
                              void* d_out, int out_size) {
    const float* x   = (const float*)d_in[0];
    const int*   ei  = (const int*)d_in[1];
    const float* ew  = (const float*)d_in[2];
    const float* W1  = (const float*)d_in[3];
    const float* b1  = (const float*)d_in[4];
    const float* W2  = (const float*)d_in[5];
    const float* b2  = (const float*)d_in[6];
    float* out = (float*)d_out;

    const int E = in_sizes[2];
    const int* src = ei;
    const int* dst = ei + E;

    // support1 = x @ W1  (TF32 mma)
    {
        float* s1;
        cudaGetSymbolAddress((void**)&s1, g_support1);
        dim3 grid(F_HID / 128, (N_NODES + G1_BM - 1) / G1_BM);
        gemm1_tf32<<<grid, 256>>>(x, W1, s1, N_NODES);
    }
    // CSR build (dst-bucketed)
    {
        const int nb = (N_NODES + 255) / 256;
        const int eb = (E + 255) / 256;
        zero_cnt<<<nb, 256>>>();
        hist_dst<<<eb, 256>>>(dst, E);
        scan_block<<<SCAN_NB, SCAN_B>>>();
        scan_top<<<1, 256>>>();
        scan_add<<<nb, 256>>>();
        fill_csr<<<eb, 256>>>(src, dst, ew, E);
    }
    // layer-1 gather, feature-chunked for L2 residency
    {
        const int blocks = (N_NODES * 32 + 255) / 256;
        gather1<<<blocks, 256>>>(b1, 0);
        gather1<<<blocks, 256>>>(b1, 128);
    }
    // support2 = relu(h1) @ W2
    gemm2_relu<<<(N_NODES / 2 + 255) / 256, 256>>>(W2);
    // out = log_softmax(b2 + gather(ew * support2[src]))
    gather2_softmax<<<(N_NODES * 32 + 255) / 256, 256>>>(b2, out);
}

// round 4
// speedup vs baseline: 2.3412x; 1.1069x over previous
#include <cuda_runtime.h>
#include <cuda_fp16.h>
#include <cstdint>

#define N_NODES 100000
#define F_IN    512
#define F_HID   256
#define F_OUT   40
#define E_MAX   3200000

#define SCAN_B  512
#define SCAN_NB ((N_NODES + SCAN_B - 1) / SCAN_B)   // 196

// ---------------- scratch (device globals; no allocation allowed) ----------
__device__ __align__(128) __half g_s1h[(size_t)N_NODES * F_HID];   // 51.2 MB (fp16 support1)
__device__ __align__(128) __half g_h1h[(size_t)N_NODES * F_HID];   // 51.2 MB (fp16 relu(h1))
__device__ __align__(128) __half g_s2h[(size_t)N_NODES * F_OUT];   // 8 MB   (fp16 support2)

__device__ int  g_cnt[N_NODES];
__device__ int  g_off[N_NODES];
__device__ int  g_pos[N_NODES];
__device__ int  g_blksum[SCAN_NB];
__device__ __align__(16) int2 g_csr[E_MAX];    // (src, float-bits of w), 25.6 MB

// ---------------- TF32 mma helpers -----------------------------------------
__device__ __forceinline__ uint32_t f2tf32(float f) {
    uint32_t r;
    asm("cvt.rna.tf32.f32 %0, %1;" : "=r"(r) : "f"(f));
    return r;
}

__device__ __forceinline__ void mma_tf32(float* c, const uint32_t* a, const uint32_t* b) {
    asm volatile("mma.sync.aligned.m16n8k8.row.col.f32.tf32.tf32.f32 "
                 "{%0,%1,%2,%3}, {%4,%5,%6,%7}, {%8,%9}, {%0,%1,%2,%3};"
                 : "+f"(c[0]), "+f"(c[1]), "+f"(c[2]), "+f"(c[3])
                 : "r"(a[0]), "r"(a[1]), "r"(a[2]), "r"(a[3]),
                   "r"(b[0]), "r"(b[1]));
}

// ================= gemm1: support1 = x @ W1  (TF32, fp16 epilogue) =========
#define G1_BM 128
#define G1_BK 16

__global__ __launch_bounds__(256) void gemm1_tf32(const float* __restrict__ A,
                                                  const float* __restrict__ B,
                                                  int M) {
    __shared__ uint32_t As[2][2][8][32][4];   // 16 KB
    __shared__ uint32_t Bs[2][2][16][32][2];  // 16 KB

    const int tid  = threadIdx.x;
    const int lane = tid & 31;
    const int warp = tid >> 5;
    const int wm = warp & 1;
    const int wn = warp >> 1;
    const int rowBase = blockIdx.y * G1_BM;
    const int colBase = blockIdx.x * 128;

    const int ar = tid >> 1;
    const int af = (tid & 1) * 2;
    const int bk  = tid >> 4;
    const int bn4 = (tid & 15) * 2;

    float acc[4][4][4];
    #pragma unroll
    for (int mt = 0; mt < 4; mt++)
        #pragma unroll
        for (int nt = 0; nt < 4; nt++)
            #pragma unroll
            for (int r = 0; r < 4; r++) acc[mt][nt][r] = 0.f;

    float4 pa[2], pb[2];
    const int arow = rowBase + ar;
    const float* Arow = A + (size_t)arow * F_IN;

    {
        pa[0] = make_float4(0.f, 0.f, 0.f, 0.f);
        pa[1] = pa[0];
        if (arow < M) {
            pa[0] = *(const float4*)(Arow + (af + 0) * 4);
            pa[1] = *(const float4*)(Arow + (af + 1) * 4);
        }
        pb[0] = *(const float4*)(B + (size_t)bk * F_HID + colBase + (bn4 + 0) * 4);
        pb[1] = *(const float4*)(B + (size_t)bk * F_HID + colBase + (bn4 + 1) * 4);
    }
    {
        const int rr = ar & 15, mt = ar >> 4;
        #pragma unroll
        for (int j = 0; j < 2; j++) {
            const int kloc = (af + j) * 4;
            const int ks = kloc >> 3;
            const int regb = (rr >> 3) + 2 * ((kloc & 7) >> 2);
            const int l0 = (rr & 7) * 4;
            As[0][ks][mt][l0 + 0][regb] = f2tf32(pa[j].x);
            As[0][ks][mt][l0 + 1][regb] = f2tf32(pa[j].y);
            As[0][ks][mt][l0 + 2][regb] = f2tf32(pa[j].z);
            As[0][ks][mt][l0 + 3][regb] = f2tf32(pa[j].w);
        }
        const int ksb = bk >> 3, kk3 = bk & 3, regB = (bk >> 2) & 1;
        #pragma unroll
        for (int j = 0; j < 2; j++) {
            const int nloc = (bn4 + j) * 4;
            const int nt = nloc >> 3, nn = nloc & 7;
            Bs[0][ksb][nt][(nn + 0) * 4 + kk3][regB] = f2tf32(pb[j].x);
            Bs[0][ksb][nt][(nn + 1) * 4 + kk3][regB] = f2tf32(pb[j].y);
            Bs[0][ksb][nt][(nn + 2) * 4 + kk3][regB] = f2tf32(pb[j].z);
            Bs[0][ksb][nt][(nn + 3) * 4 + kk3][regB] = f2tf32(pb[j].w);
        }
    }
    __syncthreads();

    const int NT = F_IN / G1_BK;
    for (int t = 0; t < NT; t++) {
        const int buf = t & 1;
        if (t + 1 < NT) {
            const int k0 = (t + 1) * G1_BK;
            pa[0] = make_float4(0.f, 0.f, 0.f, 0.f);
            pa[1] = pa[0];
            if (arow < M) {
                pa[0] = *(const float4*)(Arow + k0 + (af + 0) * 4);
                pa[1] = *(const float4*)(Arow + k0 + (af + 1) * 4);
            }
            pb[0] = *(const float4*)(B + (size_t)(k0 + bk) * F_HID + colBase + (bn4 + 0) * 4);
            pb[1] = *(const float4*)(B + (size_t)(k0 + bk) * F_HID + colBase + (bn4 + 1) * 4);
        }
        #pragma unroll
        for (int ks = 0; ks < 2; ks++) {
            uint32_t afr[4][4];
            uint32_t bfr[4][2];
            #pragma unroll
            for (int mt = 0; mt < 4; mt++) {
                uint4 v = *(const uint4*)&As[buf][ks][wm * 4 + mt][lane][0];
                afr[mt][0] = v.x; afr[mt][1] = v.y; afr[mt][2] = v.z; afr[mt][3] = v.w;
            }
            #pragma unroll
            for (int nt = 0; nt < 4; nt++) {
                uint2 v = *(const uint2*)&Bs[buf][ks][wn * 4 + nt][lane][0];
                bfr[nt][0] = v.x; bfr[nt][1] = v.y;
            }
            #pragma unroll
            for (int mt = 0; mt < 4; mt++)
                #pragma unroll
                for (int nt = 0; nt < 4; nt++)
                    mma_tf32(acc[mt][nt], afr[mt], bfr[nt]);
        }
        if (t + 1 < NT) {
            const int nb = buf ^ 1;
            const int rr = ar & 15, mt = ar >> 4;
            #pragma unroll
            for (int j = 0; j < 2; j++) {
                const int kloc = (af + j) * 4;
                const int ks = kloc >> 3;
                const int regb = (rr >> 3) + 2 * ((kloc & 7) >> 2);
                const int l0 = (rr & 7) * 4;
                As[nb][ks][mt][l0 + 0][regb] = f2tf32(pa[j].x);
                As[nb][ks][mt][l0 + 1][regb] = f2tf32(pa[j].y);
                As[nb][ks][mt][l0 + 2][regb] = f2tf32(pa[j].z);
                As[nb][ks][mt][l0 + 3][regb] = f2tf32(pa[j].w);
            }
            const int ksb = bk >> 3, kk3 = bk & 3, regB = (bk >> 2) & 1;
            #pragma unroll
            for (int j = 0; j < 2; j++) {
                const int nloc = (bn4 + j) * 4;
                const int nt = nloc >> 3, nn = nloc & 7;
                Bs[nb][ksb][nt][(nn + 0) * 4 + kk3][regB] = f2tf32(pb[j].x);
                Bs[nb][ksb][nt][(nn + 1) * 4 + kk3][regB] = f2tf32(pb[j].y);
                Bs[nb][ksb][nt][(nn + 2) * 4 + kk3][regB] = f2tf32(pb[j].z);
                Bs[nb][ksb][nt][(nn + 3) * 4 + kk3][regB] = f2tf32(pb[j].w);
            }
        }
        __syncthreads();
    }

    // epilogue: convert to fp16, store half2
    #pragma unroll
    for (int mt = 0; mt < 4; mt++) {
        const int row0 = rowBase + wm * 64 + mt * 16 + (lane >> 2);
        #pragma unroll
        for (int nt = 0; nt < 4; nt++) {
            const int col = colBase + wn * 32 + nt * 8 + (lane & 3) * 2;
            if (row0 < M)
                *(__half2*)(g_s1h + (size_t)row0 * F_HID + col) =
                    __floats2half2_rn(acc[mt][nt][0], acc[mt][nt][1]);
            if (row0 + 8 < M)
                *(__half2*)(g_s1h + (size_t)(row0 + 8) * F_HID + col) =
                    __floats2half2_rn(acc[mt][nt][2], acc[mt][nt][3]);
        }
    }
}

// ================= CSR build =================================================
__global__ void zero_cnt() {
    const int i = blockIdx.x * blockDim.x + threadIdx.x;
    if (i < N_NODES) g_cnt[i] = 0;
}

__global__ void hist_dst(const int* __restrict__ dst, int E) {
    const int e = blockIdx.x * blockDim.x + threadIdx.x;
    if (e < E) atomicAdd(&g_cnt[dst[e]], 1);
}

__global__ void scan_block() {
    __shared__ int sh[SCAN_B];
    const int t = threadIdx.x;
    const int i = blockIdx.x * SCAN_B + t;
    const int v = (i < N_NODES) ? g_cnt[i] : 0;
    sh[t] = v;
    __syncthreads();
    #pragma unroll
    for (int o = 1; o < SCAN_B; o <<= 1) {
        int x = 0;
        if (t >= o) x = sh[t - o];
        __syncthreads();
        sh[t] += x;
        __syncthreads();
    }
    if (i < N_NODES) g_off[i] = sh[t] - v;
    if (t == SCAN_B - 1) g_blksum[blockIdx.x] = sh[t];
}

__global__ void scan_top() {
    __shared__ int sh[256];
    const int t = threadIdx.x;
    const int v = (t < SCAN_NB) ? g_blksum[t] : 0;
    sh[t] = v;
    __syncthreads();
    #pragma unroll
    for (int o = 1; o < 256; o <<= 1) {
        int x = 0;
        if (t >= o) x = sh[t - o];
        __syncthreads();
        sh[t] += x;
        __syncthreads();
    }
    if (t < SCAN_NB) g_blksum[t] = sh[t] - v;
}

__global__ void scan_add() {
    const int i = blockIdx.x * blockDim.x + threadIdx.x;
    if (i < N_NODES) {
        const int o = g_off[i] + g_blksum[i / SCAN_B];
        g_off[i] = o;
        g_pos[i] = o;
    }
}

__global__ void fill_csr(const int* __restrict__ src, const int* __restrict__ dst,
                         const float* __restrict__ ew, int E) {
    const int e = blockIdx.x * blockDim.x + threadIdx.x;
    if (e < E) {
        const int p = atomicAdd(&g_pos[dst[e]], 1);
        g_csr[p] = make_int2(src[e], __float_as_int(ew[e]));
    }
}

// ======== layer-1 gather: warp per node, full 256 feats (fp16 rows) =========
__device__ __forceinline__ void accum8(float* acc, uint4 v, float w) {
    const __half2* h = (const __half2*)&v;
    #pragma unroll
    for (int j = 0; j < 4; j++) {
        const float2 f = __half22float2(h[j]);
        acc[2 * j]     = fmaf(w, f.x, acc[2 * j]);
        acc[2 * j + 1] = fmaf(w, f.y, acc[2 * j + 1]);
    }
}

__global__ __launch_bounds__(256) void gather1(const float* __restrict__ b1) {
    const int n = (blockIdx.x * blockDim.x + threadIdx.x) >> 5;
    const int lane = threadIdx.x & 31;
    if (n >= N_NODES) return;
    const int beg = g_off[n];
    const int end = beg + g_cnt[n];

    float acc[8];
    {
        const float4 blo = __ldg((const float4*)b1 + lane * 2);
        const float4 bhi = __ldg((const float4*)b1 + lane * 2 + 1);
        acc[0] = blo.x; acc[1] = blo.y; acc[2] = blo.z; acc[3] = blo.w;
        acc[4] = bhi.x; acc[5] = bhi.y; acc[6] = bhi.z; acc[7] = bhi.w;
    }

    int e = beg;
    for (; e + 3 < end; e += 4) {
        const int2 c0 = __ldg(&g_csr[e]);
        const int2 c1 = __ldg(&g_csr[e + 1]);
        const int2 c2 = __ldg(&g_csr[e + 2]);
        const int2 c3 = __ldg(&g_csr[e + 3]);
        const uint4 v0 = __ldg((const uint4*)(g_s1h + (size_t)c0.x * F_HID) + lane);
        const uint4 v1 = __ldg((const uint4*)(g_s1h + (size_t)c1.x * F_HID) + lane);
        const uint4 v2 = __ldg((const uint4*)(g_s1h + (size_t)c2.x * F_HID) + lane);
        const uint4 v3 = __ldg((const uint4*)(g_s1h + (size_t)c3.x * F_HID) + lane);
        accum8(acc, v0, __int_as_float(c0.y));
        accum8(acc, v1, __int_as_float(c1.y));
        accum8(acc, v2, __int_as_float(c2.y));
        accum8(acc, v3, __int_as_float(c3.y));
    }
    for (; e < end; e++) {
        const int2 c = __ldg(&g_csr[e]);
        const uint4 v = __ldg((const uint4*)(g_s1h + (size_t)c.x * F_HID) + lane);
        accum8(acc, v, __int_as_float(c.y));
    }

    // relu + fp16 pack + single 16B store
    uint4 o;
    __half2* ph = (__half2*)&o;
    #pragma unroll
    for (int j = 0; j < 4; j++)
        ph[j] = __floats2half2_rn(fmaxf(acc[2 * j], 0.f), fmaxf(acc[2 * j + 1], 0.f));
    ((uint4*)(g_h1h + (size_t)n * F_HID))[lane] = o;
}

// ============ gemm2: support2 = a1 @ W2 (a1 = relu'd fp16 h1) ===============
__global__ __launch_bounds__(256) void gemm2(const float* __restrict__ W2) {
    __shared__ float W2s[F_HID * F_OUT];   // 40 KB
    for (int i = threadIdx.x; i < (F_HID * F_OUT) / 4; i += 256)
        ((float4*)W2s)[i] = ((const float4*)W2)[i];
    __syncthreads();

    const int HALF = N_NODES / 2;
    const int n = blockIdx.x * blockDim.x + threadIdx.x;
    if (n >= HALF) return;

    float4 acc0[F_OUT / 4], acc1[F_OUT / 4];
    #pragma unroll
    for (int j = 0; j < F_OUT / 4; j++) {
        acc0[j] = make_float4(0.f, 0.f, 0.f, 0.f);
        acc1[j] = acc0[j];
    }

    const uint4* hr0 = (const uint4*)(g_h1h + (size_t)n * F_HID);
    const uint4* hr1 = (const uint4*)(g_h1h + (size_t)(n + HALF) * F_HID);
    for (int k8 = 0; k8 < F_HID / 8; k8++) {
        const uint4 va = __ldg(&hr0[k8]);
        const uint4 vb = __ldg(&hr1[k8]);
        const __half2* ha = (const __half2*)&va;
        const __half2* hb = (const __half2*)&vb;
        float av[8], bv[8];
        #pragma unroll
        for (int j = 0; j < 4; j++) {
            const float2 fa = __half22float2(ha[j]);
            const float2 fb = __half22float2(hb[j]);
            av[2 * j] = fa.x; av[2 * j + 1] = fa.y;
            bv[2 * j] = fb.x; bv[2 * j + 1] = fb.y;
        }
        #pragma unroll
        for (int s = 0; s < 8; s++) {
            const float a = av[s], b = bv[s];
            const float4* wrow = (const float4*)(W2s + (k8 * 8 + s) * F_OUT);
            #pragma unroll
            for (int j = 0; j < F_OUT / 4; j++) {
                const float4 wv = wrow[j];
                acc0[j].x = fmaf(a, wv.x, acc0[j].x);
                acc0[j].y = fmaf(a, wv.y, acc0[j].y);
                acc0[j].z = fmaf(a, wv.z, acc0[j].z);
                acc0[j].w = fmaf(a, wv.w, acc0[j].w);
                acc1[j].x = fmaf(b, wv.x, acc1[j].x);
                acc1[j].y = fmaf(b, wv.y, acc1[j].y);
                acc1[j].z = fmaf(b, wv.z, acc1[j].z);
                acc1[j].w = fmaf(b, wv.w, acc1[j].w);
            }
        }
    }
    __half2* o0 = (__half2*)(g_s2h + (size_t)n * F_OUT);
    __half2* o1 = (__half2*)(g_s2h + (size_t)(n + HALF) * F_OUT);
    #pragma unroll
    for (int j = 0; j < F_OUT / 4; j++) {
        o0[2 * j]     = __floats2half2_rn(acc0[j].x, acc0[j].y);
        o0[2 * j + 1] = __floats2half2_rn(acc0[j].z, acc0[j].w);
        o1[2 * j]     = __floats2half2_rn(acc1[j].x, acc1[j].y);
        o1[2 * j + 1] = __floats2half2_rn(acc1[j].z, acc1[j].w);
    }
}

// ========== layer-2 gather fused with log_softmax: warp per node ============
__global__ __launch_bounds__(256) void gather2_softmax(const float* __restrict__ b2,
                                                       float* __restrict__ out) {
    const int n = (blockIdx.x * blockDim.x + threadIdx.x) >> 5;
    const int lane = threadIdx.x & 31;
    if (n >= N_NODES) return;
    const int beg = g_off[n];
    const int end = beg + g_cnt[n];
    const bool act = lane < (F_OUT / 2);   // lanes 0..19 own features (2*lane, 2*lane+1)

    float accA = 0.f, accB = 0.f;
    if (act) {
        const float2 b = __ldg((const float2*)b2 + lane);
        accA = b.x; accB = b.y;
    }

    int e = beg;
    for (; e + 1 < end; e += 2) {
        const int2 c0 = __ldg(&g_csr[e]);
        const int2 c1 = __ldg(&g_csr[e + 1]);
        if (act) {
            const __half2 v0 = __ldg((const __half2*)(g_s2h + (size_t)c0.x * F_OUT) + lane);
            const __half2 v1 = __ldg((const __half2*)(g_s2h + (size_t)c1.x * F_OUT) + lane);
            const float w0 = __int_as_float(c0.y);
            const float w1 = __int_as_float(c1.y);
            const float2 f0 = __half22float2(v0);
            const float2 f1 = __half22float2(v1);
            accA = fmaf(w0, f0.x, accA); accB = fmaf(w0, f0.y, accB);
            accA = fmaf(w1, f1.x, accA); accB = fmaf(w1, f1.y, accB);
        }
    }
    if (e < end) {
        const int2 c = __ldg(&g_csr[e]);
        if (act) {
            const __half2 v = __ldg((const __half2*)(g_s2h + (size_t)c.x * F_OUT) + lane);
            const float w = __int_as_float(c.y);
            const float2 f = __half22float2(v);
            accA = fmaf(w, f.x, accA); accB = fmaf(w, f.y, accB);
        }
    }

    const float NEG_INF = __int_as_float(0xff800000);
    float m = act ? fmaxf(accA, accB) : NEG_INF;
    #pragma unroll
    for (int o = 16; o > 0; o >>= 1)
        m = fmaxf(m, __shfl_xor_sync(0xffffffffu, m, o));
    float s = act ? (expf(accA - m) + expf(accB - m)) : 0.f;
    #pragma unroll
    for (int o = 16; o > 0; o >>= 1)
        s += __shfl_xor_sync(0xffffffffu, s, o);
    const float l = m + logf(s);

    if (act)
        *((float2*)(out + (size_t)n * F_OUT) + lane) = make_float2(accA - l, accB - l);
}

// ---------------- launch ----------------------------------------------------
extern "C" void kernel_launch(void* const* d_in, const int* in_sizes, int n_in,
                              void* d_out, int out_size) {
    const float* x   = (const float*)d_in[0];
    const int*   ei  = (const int*)d_in[1];
    const float* ew  = (const float*)d_in[2];
    const float* W1  = (const float*)d_in[3];
    const float* b1  = (const float*)d_in[4];
    const float* W2  = (const float*)d_in[5];
    const float* b2  = (const float*)d_in[6];
    float* out = (float*)d_out;

    const int E = in_sizes[2];
    const int* src = ei;
    const int* dst = ei + E;

    // support1 = x @ W1  (TF32 mma, fp16 store)
    {
        dim3 grid(F_HID / 128, (N_NODES + G1_BM - 1) / G1_BM);
        gemm1_tf32<<<grid, 256>>>(x, W1, N_NODES);
    }
    // CSR build (dst-bucketed)
    {
        const int nb = (N_NODES + 255) / 256;
        const int eb = (E + 255) / 256;
        zero_cnt<<<nb, 256>>>();
        hist_dst<<<eb, 256>>>(dst, E);
        scan_block<<<SCAN_NB, SCAN_B>>>();
        scan_top<<<1, 256>>>();
        scan_add<<<nb, 256>>>();
        fill_csr<<<eb, 256>>>(src, dst, ew, E);
    }
    // layer-1 gather (single pass, fp16 rows L2-resident) + relu + fp16 store
    gather1<<<(N_NODES * 32 + 255) / 256, 256>>>(b1);
    // support2 = a1 @ W2
    gemm2<<<(N_NODES / 2 + 255) / 256, 256>>>(W2);
    // out = log_softmax(b2 + gather(ew * support2[src]))
    gather2_softmax<<<(N_NODES * 32 + 255) / 256, 256>>>(b2, out);
}

// round 5
// speedup vs baseline: 3.1888x; 1.3621x over previous
#include <cuda_runtime.h>
#include <cuda_fp16.h>
#include <cstdint>

#define N_NODES 100000
#define F_IN    512
#define F_HID   256
#define F_OUT   40
#define E_MAX   3200000

#define SCAN_B  512
#define SCAN_NB ((N_NODES + SCAN_B - 1) / SCAN_B)   // 196

// ---------------- scratch (device globals; no allocation allowed) ----------
__device__ __align__(128) __half g_s1h[(size_t)N_NODES * F_HID];   // 51.2 MB (fp16 support1)
__device__ __align__(128) __half g_h1h[(size_t)N_NODES * F_HID];   // 51.2 MB (fp16 relu(h1))
__device__ __align__(128) __half g_s2h[(size_t)N_NODES * F_OUT];   // 8 MB   (fp16 support2)

__device__ int  g_cnt[N_NODES];
__device__ int  g_off[N_NODES];
__device__ int  g_pos[N_NODES];
__device__ int  g_blksum[SCAN_NB];
__device__ __align__(16) int2 g_csr[E_MAX];    // (src, float-bits of w), 25.6 MB

// ---------------- fp16 mma helper -------------------------------------------
__device__ __forceinline__ void mma_f16(float* c, const uint32_t* a, const uint32_t* b) {
    asm volatile("mma.sync.aligned.m16n8k16.row.col.f32.f16.f16.f32 "
                 "{%0,%1,%2,%3}, {%4,%5,%6,%7}, {%8,%9}, {%0,%1,%2,%3};"
                 : "+f"(c[0]), "+f"(c[1]), "+f"(c[2]), "+f"(c[3])
                 : "r"(a[0]), "r"(a[1]), "r"(a[2]), "r"(a[3]),
                   "r"(b[0]), "r"(b[1]));
}

// ================= gemm1: support1 = x @ W1  (fp16 MMA, fp16 out) ==========
// Block tile 128(M) x 256(N) x 16(K); 8 warps, warp tile 64x64.
// Smem holds fragments in mma register order: A uint4/lane, B uint2/lane.
#define G1_BM 128
#define G1_BK 16

// A element (row rr 0..15 in mtile, k 0..15) -> reg=(rr>>3)+2*(k>>3),
//   lane=(rr&7)*4+((k&7)>>1), half=k&1.
__device__ __forceinline__ void g1_storeA(uint32_t (*As)[32][4],
                                          const float4* pa, int rr16, int mt, int k0) {
    const float f[8] = {pa[0].x, pa[0].y, pa[0].z, pa[0].w,
                        pa[1].x, pa[1].y, pa[1].z, pa[1].w};
    #pragma unroll
    for (int p = 0; p < 4; p++) {
        const int ke = k0 + 2 * p;
        const __half2 h = __floats2half2_rn(f[2 * p], f[2 * p + 1]);
        const int lane_t = (rr16 & 7) * 4 + ((ke & 7) >> 1);
        const int reg = (rr16 >> 3) + 2 * (ke >> 3);
        As[mt][lane_t][reg] = *(const uint32_t*)&h;
    }
}

// B element (k 0..15, n 0..255) -> nt=n>>3, lane=(n&7)*4+((k&7)>>1),
//   reg=k>>3, half=k&1.  Bs row padded to 66 words to break bank conflicts.
__device__ __forceinline__ void g1_storeB(uint32_t (*Bs)[66],
                                          const float4* pb, int bk, int bn16) {
    const int lane_half = (bk & 7) >> 1;
    const int reg = bk >> 3;
    const int hpos = bk & 1;
    #pragma unroll
    for (int i = 0; i < 4; i++) {
        const float f[4] = {pb[i].x, pb[i].y, pb[i].z, pb[i].w};
        #pragma unroll
        for (int e = 0; e < 4; e++) {
            const int n = bn16 + 4 * i + e;
            const int nt = n >> 3, nn = n & 7;
            ((__half*)&Bs[nt][(nn * 4 + lane_half) * 2 + reg])[hpos] = __float2half(f[e]);
        }
    }
}

__global__ __launch_bounds__(256, 1) void gemm1_f16(const float* __restrict__ A,
                                                    const float* __restrict__ B,
                                                    int M) {
    __shared__ __align__(16) uint32_t As[2][8][32][4];   // 8 KB
    __shared__ __align__(16) uint32_t Bs[2][32][66];     // 16.9 KB (padded)

    const int tid  = threadIdx.x;
    const int lane = tid & 31;
    const int warp = tid >> 5;
    const int wm = warp & 1;     // 0..1 -> 64-row slab
    const int wn = warp >> 1;    // 0..3 -> 64-col slab
    const int rowBase = blockIdx.x * G1_BM;

    // A fill: row = tid/2, k0 = (tid&1)*8, two float4
    const int ar = tid >> 1;
    const int ak0 = (tid & 1) * 8;
    const int amt = ar >> 4, arr = ar & 15;
    // B fill: k row = tid/16, 16 consecutive cols
    const int bk = tid >> 4;
    const int bn16 = (tid & 15) * 16;

    float acc[4][8][4];
    #pragma unroll
    for (int mt = 0; mt < 4; mt++)
        #pragma unroll
        for (int nt = 0; nt < 8; nt++)
            #pragma unroll
            for (int r = 0; r < 4; r++) acc[mt][nt][r] = 0.f;

    const int arow = rowBase + ar;
    const float* Arow = A + (size_t)arow * F_IN;
    float4 pa[2], pb[4];

    // prologue: tile 0
    {
        pa[0] = make_float4(0.f, 0.f, 0.f, 0.f); pa[1] = pa[0];
        if (arow < M) {
            pa[0] = *(const float4*)(Arow + ak0);
            pa[1] = *(const float4*)(Arow + ak0 + 4);
        }
        const float* Brow = B + (size_t)bk * F_HID + bn16;
        #pragma unroll
        for (int i = 0; i < 4; i++) pb[i] = *(const float4*)(Brow + 4 * i);
        g1_storeA(As[0], pa, arr, amt, ak0);
        g1_storeB(Bs[0], pb, bk, bn16);
    }
    __syncthreads();

    const int NT = F_IN / G1_BK;   // 32
    for (int t = 0; t < NT; t++) {
        const int buf = t & 1;
        if (t + 1 < NT) {
            const int k0 = (t + 1) * G1_BK;
            pa[0] = make_float4(0.f, 0.f, 0.f, 0.f); pa[1] = pa[0];
            if (arow < M) {
                pa[0] = *(const float4*)(Arow + k0 + ak0);
                pa[1] = *(const float4*)(Arow + k0 + ak0 + 4);
            }
            const float* Brow = B + (size_t)(k0 + bk) * F_HID + bn16;
            #pragma unroll
            for (int i = 0; i < 4; i++) pb[i] = *(const float4*)(Brow + 4 * i);
        }

        uint32_t afr[4][4];
        uint32_t bfr[8][2];
        #pragma unroll
        for (int mt = 0; mt < 4; mt++) {
            const uint4 v = *(const uint4*)&As[buf][wm * 4 + mt][lane][0];
            afr[mt][0] = v.x; afr[mt][1] = v.y; afr[mt][2] = v.z; afr[mt][3] = v.w;
        }
        #pragma unroll
        for (int nt = 0; nt < 8; nt++) {
            const uint2 v = *(const uint2*)&Bs[buf][wn * 8 + nt][lane * 2];
            bfr[nt][0] = v.x; bfr[nt][1] = v.y;
        }
        #pragma unroll
        for (int mt = 0; mt < 4; mt++)
            #pragma unroll
            for (int nt = 0; nt < 8; nt++)
                mma_f16(acc[mt][nt], afr[mt], bfr[nt]);

        if (t + 1 < NT) {
            const int nb = buf ^ 1;
            g1_storeA(As[nb], pa, arr, amt, ak0);
            g1_storeB(Bs[nb], pb, bk, bn16);
        }
        __syncthreads();
    }

    // epilogue: fp16 store
    #pragma unroll
    for (int mt = 0; mt < 4; mt++) {
        const int row0 = rowBase + wm * 64 + mt * 16 + (lane >> 2);
        #pragma unroll
        for (int nt = 0; nt < 8; nt++) {
            const int col = wn * 64 + nt * 8 + (lane & 3) * 2;
            if (row0 < M)
                *(__half2*)(g_s1h + (size_t)row0 * F_HID + col) =
                    __floats2half2_rn(acc[mt][nt][0], acc[mt][nt][1]);
            if (row0 + 8 < M)
                *(__half2*)(g_s1h + (size_t)(row0 + 8) * F_HID + col) =
                    __floats2half2_rn(acc[mt][nt][2], acc[mt][nt][3]);
        }
    }
}

// ================= CSR build =================================================
__global__ void zero_cnt() {
    const int i = blockIdx.x * blockDim.x + threadIdx.x;
    if (i < N_NODES) g_cnt[i] = 0;
}

__global__ void hist_dst(const int* __restrict__ dst, int E) {
    const int e = blockIdx.x * blockDim.x + threadIdx.x;
    if (e < E) atomicAdd(&g_cnt[dst[e]], 1);
}

__global__ void scan_block() {
    __shared__ int sh[SCAN_B];
    const int t = threadIdx.x;
    const int i = blockIdx.x * SCAN_B + t;
    const int v = (i < N_NODES) ? g_cnt[i] : 0;
    sh[t] = v;
    __syncthreads();
    #pragma unroll
    for (int o = 1; o < SCAN_B; o <<= 1) {
        int x = 0;
        if (t >= o) x = sh[t - o];
        __syncthreads();
        sh[t] += x;
        __syncthreads();
    }
    if (i < N_NODES) g_off[i] = sh[t] - v;
    if (t == SCAN_B - 1) g_blksum[blockIdx.x] = sh[t];
}

__global__ void scan_top() {
    __shared__ int sh[256];
    const int t = threadIdx.x;
    const int v = (t < SCAN_NB) ? g_blksum[t] : 0;
    sh[t] = v;
    __syncthreads();
    #pragma unroll
    for (int o = 1; o < 256; o <<= 1) {
        int x = 0;
        if (t >= o) x = sh[t - o];
        __syncthreads();
        sh[t] += x;
        __syncthreads();
    }
    if (t < SCAN_NB) g_blksum[t] = sh[t] - v;
}

__global__ void scan_add() {
    const int i = blockIdx.x * blockDim.x + threadIdx.x;
    if (i < N_NODES) {
        const int o = g_off[i] + g_blksum[i / SCAN_B];
        g_off[i] = o;
        g_pos[i] = o;
    }
}

__global__ void fill_csr(const int* __restrict__ src, const int* __restrict__ dst,
                         const float* __restrict__ ew, int E) {
    const int e = blockIdx.x * blockDim.x + threadIdx.x;
    if (e < E) {
        const int p = atomicAdd(&g_pos[dst[e]], 1);
        g_csr[p] = make_int2(src[e], __float_as_int(ew[e]));
    }
}

// ======== layer-1 gather: warp per node, full 256 feats (fp16 rows) =========
__device__ __forceinline__ void accum8(float* acc, uint4 v, float w) {
    const __half2* h = (const __half2*)&v;
    #pragma unroll
    for (int j = 0; j < 4; j++) {
        const float2 f = __half22float2(h[j]);
        acc[2 * j]     = fmaf(w, f.x, acc[2 * j]);
        acc[2 * j + 1] = fmaf(w, f.y, acc[2 * j + 1]);
    }
}

__global__ __launch_bounds__(256) void gather1(const float* __restrict__ b1) {
    const int n = (blockIdx.x * blockDim.x + threadIdx.x) >> 5;
    const int lane = threadIdx.x & 31;
    if (n >= N_NODES) return;
    const int beg = g_off[n];
    const int end = beg + g_cnt[n];

    float acc[8];
    {
        const float4 blo = __ldg((const float4*)b1 + lane * 2);
        const float4 bhi = __ldg((const float4*)b1 + lane * 2 + 1);
        acc[0] = blo.x; acc[1] = blo.y; acc[2] = blo.z; acc[3] = blo.w;
        acc[4] = bhi.x; acc[5] = bhi.y; acc[6] = bhi.z; acc[7] = bhi.w;
    }

    int e = beg;
    for (; e + 3 < end; e += 4) {
        const int2 c0 = __ldg(&g_csr[e]);
        const int2 c1 = __ldg(&g_csr[e + 1]);
        const int2 c2 = __ldg(&g_csr[e + 2]);
        const int2 c3 = __ldg(&g_csr[e + 3]);
        const uint4 v0 = __ldg((const uint4*)(g_s1h + (size_t)c0.x * F_HID) + lane);
        const uint4 v1 = __ldg((const uint4*)(g_s1h + (size_t)c1.x * F_HID) + lane);
        const uint4 v2 = __ldg((const uint4*)(g_s1h + (size_t)c2.x * F_HID) + lane);
        const uint4 v3 = __ldg((const uint4*)(g_s1h + (size_t)c3.x * F_HID) + lane);
        accum8(acc, v0, __int_as_float(c0.y));
        accum8(acc, v1, __int_as_float(c1.y));
        accum8(acc, v2, __int_as_float(c2.y));
        accum8(acc, v3, __int_as_float(c3.y));
    }
    for (; e < end; e++) {
        const int2 c = __ldg(&g_csr[e]);
        const uint4 v = __ldg((const uint4*)(g_s1h + (size_t)c.x * F_HID) + lane);
        accum8(acc, v, __int_as_float(c.y));
    }

    uint4 o;
    __half2* ph = (__half2*)&o;
    #pragma unroll
    for (int j = 0; j < 4; j++)
        ph[j] = __floats2half2_rn(fmaxf(acc[2 * j], 0.f), fmaxf(acc[2 * j + 1], 0.f));
    ((uint4*)(g_h1h + (size_t)n * F_HID))[lane] = o;
}

// ============ gemm2: support2 = a1 @ W2 (a1 = relu'd fp16 h1) ===============
__global__ __launch_bounds__(256) void gemm2(const float* __restrict__ W2) {
    __shared__ float W2s[F_HID * F_OUT];   // 40 KB
    for (int i = threadIdx.x; i < (F_HID * F_OUT) / 4; i += 256)
        ((float4*)W2s)[i] = ((const float4*)W2)[i];
    __syncthreads();

    const int HALF = N_NODES / 2;
    const int n = blockIdx.x * blockDim.x + threadIdx.x;
    if (n >= HALF) return;

    float4 acc0[F_OUT / 4], acc1[F_OUT / 4];
    #pragma unroll
    for (int j = 0; j < F_OUT / 4; j++) {
        acc0[j] = make_float4(0.f, 0.f, 0.f, 0.f);
        acc1[j] = acc0[j];
    }

    const uint4* hr0 = (const uint4*)(g_h1h + (size_t)n * F_HID);
    const uint4* hr1 = (const uint4*)(g_h1h + (size_t)(n + HALF) * F_HID);
    for (int k8 = 0; k8 < F_HID / 8; k8++) {
        const uint4 va = __ldg(&hr0[k8]);
        const uint4 vb = __ldg(&hr1[k8]);
        const __half2* ha = (const __half2*)&va;
        const __half2* hb = (const __half2*)&vb;
        float av[8], bv[8];
        #pragma unroll
        for (int j = 0; j < 4; j++) {
            const float2 fa = __half22float2(ha[j]);
            const float2 fb = __half22float2(hb[j]);
            av[2 * j] = fa.x; av[2 * j + 1] = fa.y;
            bv[2 * j] = fb.x; bv[2 * j + 1] = fb.y;
        }
        #pragma unroll
        for (int s = 0; s < 8; s++) {
            const float a = av[s], b = bv[s];
            const float4* wrow = (const float4*)(W2s + (k8 * 8 + s) * F_OUT);
            #pragma unroll
            for (int j = 0; j < F_OUT / 4; j++) {
                const float4 wv = wrow[j];
                acc0[j].x = fmaf(a, wv.x, acc0[j].x);
                acc0[j].y = fmaf(a, wv.y, acc0[j].y);
                acc0[j].z = fmaf(a, wv.z, acc0[j].z);
                acc0[j].w = fmaf(a, wv.w, acc0[j].w);
                acc1[j].x = fmaf(b, wv.x, acc1[j].x);
                acc1[j].y = fmaf(b, wv.y, acc1[j].y);
                acc1[j].z = fmaf(b, wv.z, acc1[j].z);
                acc1[j].w = fmaf(b, wv.w, acc1[j].w);
            }
        }
    }
    __half2* o0 = (__half2*)(g_s2h + (size_t)n * F_OUT);
    __half2* o1 = (__half2*)(g_s2h + (size_t)(n + HALF) * F_OUT);
    #pragma unroll
    for (int j = 0; j < F_OUT / 4; j++) {
        o0[2 * j]     = __floats2half2_rn(acc0[j].x, acc0[j].y);
        o0[2 * j + 1] = __floats2half2_rn(acc0[j].z, acc0[j].w);
        o1[2 * j]     = __floats2half2_rn(acc1[j].x, acc1[j].y);
        o1[2 * j + 1] = __floats2half2_rn(acc1[j].z, acc1[j].w);
    }
}

// ========== layer-2 gather fused with log_softmax: warp per node ============
__global__ __launch_bounds__(256) void gather2_softmax(const float* __restrict__ b2,
                                                       float* __restrict__ out) {
    const int n = (blockIdx.x * blockDim.x + threadIdx.x) >> 5;
    const int lane = threadIdx.x & 31;
    if (n >= N_NODES) return;
    const int beg = g_off[n];
    const int end = beg + g_cnt[n];
    const bool act = lane < (F_OUT / 2);

    float accA = 0.f, accB = 0.f;
    if (act) {
        const float2 b = __ldg((const float2*)b2 + lane);
        accA = b.x; accB = b.y;
    }

    int e = beg;
    for (; e + 1 < end; e += 2) {
        const int2 c0 = __ldg(&g_csr[e]);
        const int2 c1 = __ldg(&g_csr[e + 1]);
        if (act) {
            const __half2 v0 = __ldg((const __half2*)(g_s2h + (size_t)c0.x * F_OUT) + lane);
            const __half2 v1 = __ldg((const __half2*)(g_s2h + (size_t)c1.x * F_OUT) + lane);
            const float w0 = __int_as_float(c0.y);
            const float w1 = __int_as_float(c1.y);
            const float2 f0 = __half22float2(v0);
            const float2 f1 = __half22float2(v1);
            accA = fmaf(w0, f0.x, accA); accB = fmaf(w0, f0.y, accB);
            accA = fmaf(w1, f1.x, accA); accB = fmaf(w1, f1.y, accB);
        }
    }
    if (e < end) {
        const int2 c = __ldg(&g_csr[e]);
        if (act) {
            const __half2 v = __ldg((const __half2*)(g_s2h + (size_t)c.x * F_OUT) + lane);
            const float w = __int_as_float(c.y);
            const float2 f = __half22float2(v);
            accA = fmaf(w, f.x, accA); accB = fmaf(w, f.y, accB);
        }
    }

    const float NEG_INF = __int_as_float(0xff800000);
    float m = act ? fmaxf(accA, accB) : NEG_INF;
    #pragma unroll
    for (int o = 16; o > 0; o >>= 1)
        m = fmaxf(m, __shfl_xor_sync(0xffffffffu, m, o));
    float s = act ? (expf(accA - m) + expf(accB - m)) : 0.f;
    #pragma unroll
    for (int o = 16; o > 0; o >>= 1)
        s += __shfl_xor_sync(0xffffffffu, s, o);
    const float l = m + logf(s);

    if (act)
        *((float2*)(out + (size_t)n * F_OUT) + lane) = make_float2(accA - l, accB - l);
}

// ---------------- launch ----------------------------------------------------
extern "C" void kernel_launch(void* const* d_in, const int* in_sizes, int n_in,
                              void* d_out, int out_size) {
    const float* x   = (const float*)d_in[0];
    const int*   ei  = (const int*)d_in[1];
    const float* ew  = (const float*)d_in[2];
    const float* W1  = (const float*)d_in[3];
    const float* b1  = (const float*)d_in[4];
    const float* W2  = (const float*)d_in[5];
    const float* b2  = (const float*)d_in[6];
    float* out = (float*)d_out;

    const int E = in_sizes[2];
    const int* src = ei;
    const int* dst = ei + E;

    // support1 = x @ W1  (fp16 mma, fp16 store, single pass over x)
    gemm1_f16<<<(N_NODES + G1_BM - 1) / G1_BM, 256>>>(x, W1, N_NODES);

    // CSR build (dst-bucketed)
    {
        const int nb = (N_NODES + 255) / 256;
        const int eb = (E + 255) / 256;
        zero_cnt<<<nb, 256>>>();
        hist_dst<<<eb, 256>>>(dst, E);
        scan_block<<<SCAN_NB, SCAN_B>>>();
        scan_top<<<1, 256>>>();
        scan_add<<<nb, 256>>>();
        fill_csr<<<eb, 256>>>(src, dst, ew, E);
    }
    // layer-1 gather (single pass, fp16 rows L2-resident) + relu + fp16 store
    gather1<<<(N_NODES * 32 + 255) / 256, 256>>>(b1);
    // support2 = a1 @ W2
    gemm2<<<(N_NODES / 2 + 255) / 256, 256>>>(W2);
    // out = log_softmax(b2 + gather(ew * support2[src]))
    gather2_softmax<<<(N_NODES * 32 + 255) / 256, 256>>>(b2, out);
}

// round 6
// speedup vs baseline: 3.4697x; 1.0881x over previous
#include <cuda_runtime.h>
#include <cuda_fp16.h>
#include <cstdint>

#define N_NODES 100000
#define F_IN    512
#define F_HID   256
#define F_OUT   40
#define E_MAX   3200000

#define SCAN_B  512
#define SCAN_NB ((N_NODES + SCAN_B - 1) / SCAN_B)   // 196

// ---------------- scratch (device globals; no allocation allowed) ----------
__device__ __align__(128) __half g_s1h[(size_t)N_NODES * F_HID];   // 51.2 MB (fp16 support1)
__device__ __align__(128) __half g_h1h[(size_t)N_NODES * F_HID];   // 51.2 MB (fp16 relu(h1))
__device__ __align__(128) __half g_s2h[(size_t)N_NODES * F_OUT];   // 8 MB   (fp16 support2)

__device__ int  g_cnt[N_NODES];
__device__ int  g_off[N_NODES];
__device__ int  g_pos[N_NODES];
__device__ int  g_blksum[SCAN_NB];
__device__ __align__(16) int2 g_csr[E_MAX];    // (src, float-bits of w), 25.6 MB

// ---------------- fp16 mma helper -------------------------------------------
__device__ __forceinline__ void mma_f16(float* c, const uint32_t* a, const uint32_t* b) {
    asm volatile("mma.sync.aligned.m16n8k16.row.col.f32.f16.f16.f32 "
                 "{%0,%1,%2,%3}, {%4,%5,%6,%7}, {%8,%9}, {%0,%1,%2,%3};"
                 : "+f"(c[0]), "+f"(c[1]), "+f"(c[2]), "+f"(c[3])
                 : "r"(a[0]), "r"(a[1]), "r"(a[2]), "r"(a[3]),
                   "r"(b[0]), "r"(b[1]));
}

// ================= gemm1: support1 = x @ W1  (fp16 MMA, fp16 out) ==========
#define G1_BM 128
#define G1_BK 16

__device__ __forceinline__ void g1_storeA(uint32_t (*As)[32][4],
                                          const float4* pa, int rr16, int mt, int k0) {
    const float f[8] = {pa[0].x, pa[0].y, pa[0].z, pa[0].w,
                        pa[1].x, pa[1].y, pa[1].z, pa[1].w};
    #pragma unroll
    for (int p = 0; p < 4; p++) {
        const int ke = k0 + 2 * p;
        const __half2 h = __floats2half2_rn(f[2 * p], f[2 * p + 1]);
        const int lane_t = (rr16 & 7) * 4 + ((ke & 7) >> 1);
        const int reg = (rr16 >> 3) + 2 * (ke >> 3);
        As[mt][lane_t][reg] = *(const uint32_t*)&h;
    }
}

__device__ __forceinline__ void g1_storeB(uint32_t (*Bs)[66],
                                          const float4* pb, int bk, int bn16) {
    const int lane_half = (bk & 7) >> 1;
    const int reg = bk >> 3;
    const int hpos = bk & 1;
    #pragma unroll
    for (int i = 0; i < 4; i++) {
        const float f[4] = {pb[i].x, pb[i].y, pb[i].z, pb[i].w};
        #pragma unroll
        for (int e = 0; e < 4; e++) {
            const int n = bn16 + 4 * i + e;
            const int nt = n >> 3, nn = n & 7;
            ((__half*)&Bs[nt][(nn * 4 + lane_half) * 2 + reg])[hpos] = __float2half(f[e]);
        }
    }
}

__global__ __launch_bounds__(256, 1) void gemm1_f16(const float* __restrict__ A,
                                                    const float* __restrict__ B,
                                                    int M) {
    __shared__ __align__(16) uint32_t As[2][8][32][4];   // 8 KB
    __shared__ __align__(16) uint32_t Bs[2][32][66];     // 16.9 KB (padded)

    const int tid  = threadIdx.x;
    const int lane = tid & 31;
    const int warp = tid >> 5;
    const int wm = warp & 1;
    const int wn = warp >> 1;
    const int rowBase = blockIdx.x * G1_BM;

    const int ar = tid >> 1;
    const int ak0 = (tid & 1) * 8;
    const int amt = ar >> 4, arr = ar & 15;
    const int bk = tid >> 4;
    const int bn16 = (tid & 15) * 16;

    float acc[4][8][4];
    #pragma unroll
    for (int mt = 0; mt < 4; mt++)
        #pragma unroll
        for (int nt = 0; nt < 8; nt++)
            #pragma unroll
            for (int r = 0; r < 4; r++) acc[mt][nt][r] = 0.f;

    const int arow = rowBase + ar;
    const float* Arow = A + (size_t)arow * F_IN;
    float4 pa[2], pb[4];

    {
        pa[0] = make_float4(0.f, 0.f, 0.f, 0.f); pa[1] = pa[0];
        if (arow < M) {
            pa[0] = *(const float4*)(Arow + ak0);
            pa[1] = *(const float4*)(Arow + ak0 + 4);
        }
        const float* Brow = B + (size_t)bk * F_HID + bn16;
        #pragma unroll
        for (int i = 0; i < 4; i++) pb[i] = *(const float4*)(Brow + 4 * i);
        g1_storeA(As[0], pa, arr, amt, ak0);
        g1_storeB(Bs[0], pb, bk, bn16);
    }
    __syncthreads();

    const int NT = F_IN / G1_BK;   // 32
    for (int t = 0; t < NT; t++) {
        const int buf = t & 1;
        if (t + 1 < NT) {
            const int k0 = (t + 1) * G1_BK;
            pa[0] = make_float4(0.f, 0.f, 0.f, 0.f); pa[1] = pa[0];
            if (arow < M) {
                pa[0] = *(const float4*)(Arow + k0 + ak0);
                pa[1] = *(const float4*)(Arow + k0 + ak0 + 4);
            }
            const float* Brow = B + (size_t)(k0 + bk) * F_HID + bn16;
            #pragma unroll
            for (int i = 0; i < 4; i++) pb[i] = *(const float4*)(Brow + 4 * i);
        }

        uint32_t afr[4][4];
        uint32_t bfr[8][2];
        #pragma unroll
        for (int mt = 0; mt < 4; mt++) {
            const uint4 v = *(const uint4*)&As[buf][wm * 4 + mt][lane][0];
            afr[mt][0] = v.x; afr[mt][1] = v.y; afr[mt][2] = v.z; afr[mt][3] = v.w;
        }
        #pragma unroll
        for (int nt = 0; nt < 8; nt++) {
            const uint2 v = *(const uint2*)&Bs[buf][wn * 8 + nt][lane * 2];
            bfr[nt][0] = v.x; bfr[nt][1] = v.y;
        }
        #pragma unroll
        for (int mt = 0; mt < 4; mt++)
            #pragma unroll
            for (int nt = 0; nt < 8; nt++)
                mma_f16(acc[mt][nt], afr[mt], bfr[nt]);

        if (t + 1 < NT) {
            const int nb = buf ^ 1;
            g1_storeA(As[nb], pa, arr, amt, ak0);
            g1_storeB(Bs[nb], pb, bk, bn16);
        }
        __syncthreads();
    }

    #pragma unroll
    for (int mt = 0; mt < 4; mt++) {
        const int row0 = rowBase + wm * 64 + mt * 16 + (lane >> 2);
        #pragma unroll
        for (int nt = 0; nt < 8; nt++) {
            const int col = wn * 64 + nt * 8 + (lane & 3) * 2;
            if (row0 < M)
                *(__half2*)(g_s1h + (size_t)row0 * F_HID + col) =
                    __floats2half2_rn(acc[mt][nt][0], acc[mt][nt][1]);
            if (row0 + 8 < M)
                *(__half2*)(g_s1h + (size_t)(row0 + 8) * F_HID + col) =
                    __floats2half2_rn(acc[mt][nt][2], acc[mt][nt][3]);
        }
    }
}

// ================= CSR build =================================================
__global__ void zero_cnt() {
    const int i = blockIdx.x * blockDim.x + threadIdx.x;
    if (i < N_NODES) g_cnt[i] = 0;
}

__global__ void hist_dst(const int* __restrict__ dst, int E) {
    const int e = blockIdx.x * blockDim.x + threadIdx.x;
    if (e < E) atomicAdd(&g_cnt[dst[e]], 1);
}

__global__ void scan_block() {
    __shared__ int sh[SCAN_B];
    const int t = threadIdx.x;
    const int i = blockIdx.x * SCAN_B + t;
    const int v = (i < N_NODES) ? g_cnt[i] : 0;
    sh[t] = v;
    __syncthreads();
    #pragma unroll
    for (int o = 1; o < SCAN_B; o <<= 1) {
        int x = 0;
        if (t >= o) x = sh[t - o];
        __syncthreads();
        sh[t] += x;
        __syncthreads();
    }
    if (i < N_NODES) g_off[i] = sh[t] - v;
    if (t == SCAN_B - 1) g_blksum[blockIdx.x] = sh[t];
}

__global__ void scan_top() {
    __shared__ int sh[256];
    const int t = threadIdx.x;
    const int v = (t < SCAN_NB) ? g_blksum[t] : 0;
    sh[t] = v;
    __syncthreads();
    #pragma unroll
    for (int o = 1; o < 256; o <<= 1) {
        int x = 0;
        if (t >= o) x = sh[t - o];
        __syncthreads();
        sh[t] += x;
        __syncthreads();
    }
    if (t < SCAN_NB) g_blksum[t] = sh[t] - v;
}

__global__ void scan_add() {
    const int i = blockIdx.x * blockDim.x + threadIdx.x;
    if (i < N_NODES) {
        const int o = g_off[i] + g_blksum[i / SCAN_B];
        g_off[i] = o;
        g_pos[i] = o;
    }
}

__global__ void fill_csr(const int* __restrict__ src, const int* __restrict__ dst,
                         const float* __restrict__ ew, int E) {
    const int e = blockIdx.x * blockDim.x + threadIdx.x;
    if (e < E) {
        const int p = atomicAdd(&g_pos[dst[e]], 1);
        g_csr[p] = make_int2(src[e], __float_as_int(ew[e]));
    }
}

// ======== layer-1 gather: warp per node, full 256 feats (fp16 rows) =========
__device__ __forceinline__ void accum8(float* acc, uint4 v, float w) {
    const __half2* h = (const __half2*)&v;
    #pragma unroll
    for (int j = 0; j < 4; j++) {
        const float2 f = __half22float2(h[j]);
        acc[2 * j]     = fmaf(w, f.x, acc[2 * j]);
        acc[2 * j + 1] = fmaf(w, f.y, acc[2 * j + 1]);
    }
}

__global__ __launch_bounds__(256) void gather1(const float* __restrict__ b1) {
    const int n = (blockIdx.x * blockDim.x + threadIdx.x) >> 5;
    const int lane = threadIdx.x & 31;
    if (n >= N_NODES) return;
    const int beg = g_off[n];
    const int end = beg + g_cnt[n];

    float acc[8];
    {
        const float4 blo = __ldg((const float4*)b1 + lane * 2);
        const float4 bhi = __ldg((const float4*)b1 + lane * 2 + 1);
        acc[0] = blo.x; acc[1] = blo.y; acc[2] = blo.z; acc[3] = blo.w;
        acc[4] = bhi.x; acc[5] = bhi.y; acc[6] = bhi.z; acc[7] = bhi.w;
    }

    int e = beg;
    for (; e + 7 < end; e += 8) {
        int2 c[8];
        uint4 v[8];
        #pragma unroll
        for (int i = 0; i < 8; i++) c[i] = __ldg(&g_csr[e + i]);
        #pragma unroll
        for (int i = 0; i < 8; i++)
            v[i] = __ldg((const uint4*)(g_s1h + (size_t)c[i].x * F_HID) + lane);
        #pragma unroll
        for (int i = 0; i < 8; i++) accum8(acc, v[i], __int_as_float(c[i].y));
    }
    for (; e < end; e++) {
        const int2 c = __ldg(&g_csr[e]);
        const uint4 v = __ldg((const uint4*)(g_s1h + (size_t)c.x * F_HID) + lane);
        accum8(acc, v, __int_as_float(c.y));
    }

    uint4 o;
    __half2* ph = (__half2*)&o;
    #pragma unroll
    for (int j = 0; j < 4; j++)
        ph[j] = __floats2half2_rn(fmaxf(acc[2 * j], 0.f), fmaxf(acc[2 * j + 1], 0.f));
    ((uint4*)(g_h1h + (size_t)n * F_HID))[lane] = o;
}

// ============ gemm2: support2 = a1 @ W2 (a1 = relu'd fp16 h1) ===============
__global__ __launch_bounds__(256) void gemm2(const float* __restrict__ W2) {
    __shared__ float W2s[F_HID * F_OUT];   // 40 KB
    for (int i = threadIdx.x; i < (F_HID * F_OUT) / 4; i += 256)
        ((float4*)W2s)[i] = ((const float4*)W2)[i];
    __syncthreads();

    const int HALF = N_NODES / 2;
    const int n = blockIdx.x * blockDim.x + threadIdx.x;
    if (n >= HALF) return;

    float4 acc0[F_OUT / 4], acc1[F_OUT / 4];
    #pragma unroll
    for (int j = 0; j < F_OUT / 4; j++) {
        acc0[j] = make_float4(0.f, 0.f, 0.f, 0.f);
        acc1[j] = acc0[j];
    }

    const uint4* hr0 = (const uint4*)(g_h1h + (size_t)n * F_HID);
    const uint4* hr1 = (const uint4*)(g_h1h + (size_t)(n + HALF) * F_HID);
    for (int k8 = 0; k8 < F_HID / 8; k8++) {
        const uint4 va = __ldg(&hr0[k8]);
        const uint4 vb = __ldg(&hr1[k8]);
        const __half2* ha = (const __half2*)&va;
        const __half2* hb = (const __half2*)&vb;
        float av[8], bv[8];
        #pragma unroll
        for (int j = 0; j < 4; j++) {
            const float2 fa = __half22float2(ha[j]);
            const float2 fb = __half22float2(hb[j]);
            av[2 * j] = fa.x; av[2 * j + 1] = fa.y;
            bv[2 * j] = fb.x; bv[2 * j + 1] = fb.y;
        }
        #pragma unroll
        for (int s = 0; s < 8; s++) {
            const float a = av[s], b = bv[s];
            const float4* wrow = (const float4*)(W2s + (k8 * 8 + s) * F_OUT);
            #pragma unroll
            for (int j = 0; j < F_OUT / 4; j++) {
                const float4 wv = wrow[j];
                acc0[j].x = fmaf(a, wv.x, acc0[j].x);
                acc0[j].y = fmaf(a, wv.y, acc0[j].y);
                acc0[j].z = fmaf(a, wv.z, acc0[j].z);
                acc0[j].w = fmaf(a, wv.w, acc0[j].w);
                acc1[j].x = fmaf(b, wv.x, acc1[j].x);
                acc1[j].y = fmaf(b, wv.y, acc1[j].y);
                acc1[j].z = fmaf(b, wv.z, acc1[j].z);
                acc1[j].w = fmaf(b, wv.w, acc1[j].w);
            }
        }
    }
    __half2* o0 = (__half2*)(g_s2h + (size_t)n * F_OUT);
    __half2* o1 = (__half2*)(g_s2h + (size_t)(n + HALF) * F_OUT);
    #pragma unroll
    for (int j = 0; j < F_OUT / 4; j++) {
        o0[2 * j]     = __floats2half2_rn(acc0[j].x, acc0[j].y);
        o0[2 * j + 1] = __floats2half2_rn(acc0[j].z, acc0[j].w);
        o1[2 * j]     = __floats2half2_rn(acc1[j].x, acc1[j].y);
        o1[2 * j + 1] = __floats2half2_rn(acc1[j].z, acc1[j].w);
    }
}

// ========== layer-2 gather fused with log_softmax: warp per node ============
__global__ __launch_bounds__(256) void gather2_softmax(const float* __restrict__ b2,
                                                       float* __restrict__ out) {
    const int n = (blockIdx.x * blockDim.x + threadIdx.x) >> 5;
    const int lane = threadIdx.x & 31;
    if (n >= N_NODES) return;
    const int beg = g_off[n];
    const int end = beg + g_cnt[n];
    const bool act = lane < (F_OUT / 2);

    float accA = 0.f, accB = 0.f;
    if (act) {
        const float2 b = __ldg((const float2*)b2 + lane);
        accA = b.x; accB = b.y;
    }

    int e = beg;
    for (; e + 1 < end; e += 2) {
        const int2 c0 = __ldg(&g_csr[e]);
        const int2 c1 = __ldg(&g_csr[e + 1]);
        if (act) {
            const __half2 v0 = __ldg((const __half2*)(g_s2h + (size_t)c0.x * F_OUT) + lane);
            const __half2 v1 = __ldg((const __half2*)(g_s2h + (size_t)c1.x * F_OUT) + lane);
            const float w0 = __int_as_float(c0.y);
            const float w1 = __int_as_float(c1.y);
            const float2 f0 = __half22float2(v0);
            const float2 f1 = __half22float2(v1);
            accA = fmaf(w0, f0.x, accA); accB = fmaf(w0, f0.y, accB);
            accA = fmaf(w1, f1.x, accA); accB = fmaf(w1, f1.y, accB);
        }
    }
    if (e < end) {
        const int2 c = __ldg(&g_csr[e]);
        if (act) {
            const __half2 v = __ldg((const __half2*)(g_s2h + (size_t)c.x * F_OUT) + lane);
            const float w = __int_as_float(c.y);
            const float2 f = __half22float2(v);
            accA = fmaf(w, f.x, accA); accB = fmaf(w, f.y, accB);
        }
    }

    const float NEG_INF = __int_as_float(0xff800000);
    float m = act ? fmaxf(accA, accB) : NEG_INF;
    #pragma unroll
    for (int o = 16; o > 0; o >>= 1)
        m = fmaxf(m, __shfl_xor_sync(0xffffffffu, m, o));
    float s = act ? (expf(accA - m) + expf(accB - m)) : 0.f;
    #pragma unroll
    for (int o = 16; o > 0; o >>= 1)
        s += __shfl_xor_sync(0xffffffffu, s, o);
    const float l = m + logf(s);

    if (act)
        *((float2*)(out + (size_t)n * F_OUT) + lane) = make_float2(accA - l, accB - l);
}

// ---------------- launch ----------------------------------------------------
extern "C" void kernel_launch(void* const* d_in, const int* in_sizes, int n_in,
                              void* d_out, int out_size) {
    const float* x   = (const float*)d_in[0];
    const int*   ei  = (const int*)d_in[1];
    const float* ew  = (const float*)d_in[2];
    const float* W1  = (const float*)d_in[3];
    const float* b1  = (const float*)d_in[4];
    const float* W2  = (const float*)d_in[5];
    const float* b2  = (const float*)d_in[6];
    float* out = (float*)d_out;

    const int E = in_sizes[2];
    const int* src = ei;
    const int* dst = ei + E;

    // Fork: CSR build runs concurrently with gemm1 (independent data).
    cudaStream_t s2;
    cudaStreamCreate(&s2);
    cudaEvent_t evFork, evJoin;
    cudaEventCreateWithFlags(&evFork, cudaEventDisableTiming);
    cudaEventCreateWithFlags(&evJoin, cudaEventDisableTiming);

    cudaEventRecord(evFork, 0);
    cudaStreamWaitEvent(s2, evFork, 0);

    // branch A (main stream): support1 = x @ W1
    gemm1_f16<<<(N_NODES + G1_BM - 1) / G1_BM, 256>>>(x, W1, N_NODES);

    // branch B (side stream): CSR build (dst-bucketed)
    {
        const int nb = (N_NODES + 255) / 256;
        const int eb = (E + 255) / 256;
        zero_cnt<<<nb, 256, 0, s2>>>();
        hist_dst<<<eb, 256, 0, s2>>>(dst, E);
        scan_block<<<SCAN_NB, SCAN_B, 0, s2>>>();
        scan_top<<<1, 256, 0, s2>>>();
        scan_add<<<nb, 256, 0, s2>>>();
        fill_csr<<<eb, 256, 0, s2>>>(src, dst, ew, E);
    }

    cudaEventRecord(evJoin, s2);
    cudaStreamWaitEvent(0, evJoin, 0);

    // layer-1 gather (needs both branches) + relu + fp16 store
    gather1<<<(N_NODES * 32 + 255) / 256, 256>>>(b1);
    // support2 = a1 @ W2
    gemm2<<<(N_NODES / 2 + 255) / 256, 256>>>(W2);
    // out = log_softmax(b2 + gather(ew * support2[src]))
    gather2_softmax<<<(N_NODES * 32 + 255) / 256, 256>>>(b2, out);

    cudaStreamDestroy(s2);
    cudaEventDestroy(evFork);
    cudaEventDestroy(evJoin);
}

// round 7
// speedup vs baseline: 3.8022x; 1.0958x over previous
#include <cuda_runtime.h>
#include <cuda_fp16.h>
#include <cstdint>

#define N_NODES 100000
#define F_IN    512
#define F_HID   256
#define F_OUT   40
#define E_MAX   3200000

#define SCAN_B  512
#define SCAN_NB ((N_NODES + SCAN_B - 1) / SCAN_B)   // 196

// ---------------- scratch (device globals; no allocation allowed) ----------
__device__ __align__(128) __half g_s1h[(size_t)N_NODES * F_HID];   // 51.2 MB (fp16 support1)
__device__ __align__(128) __half g_h1h[(size_t)N_NODES * F_HID];   // 51.2 MB (fp16 relu(h1))
__device__ __align__(128) __half g_s2h[(size_t)N_NODES * F_OUT];   // 8 MB   (fp16 support2)

__device__ int  g_cnt[N_NODES];
__device__ int  g_off[N_NODES];
__device__ int  g_pos[N_NODES];
__device__ int  g_blksum[SCAN_NB];
__device__ __align__(16) int2 g_csr[E_MAX];    // (src, float-bits of w), 25.6 MB

// ---------------- fp16 mma helper -------------------------------------------
__device__ __forceinline__ void mma_f16(float* c, const uint32_t* a, const uint32_t* b) {
    asm volatile("mma.sync.aligned.m16n8k16.row.col.f32.f16.f16.f32 "
                 "{%0,%1,%2,%3}, {%4,%5,%6,%7}, {%8,%9}, {%0,%1,%2,%3};"
                 : "+f"(c[0]), "+f"(c[1]), "+f"(c[2]), "+f"(c[3])
                 : "r"(a[0]), "r"(a[1]), "r"(a[2]), "r"(a[3]),
                   "r"(b[0]), "r"(b[1]));
}

// ================= gemm1: support1 = x @ W1  (fp16 MMA, fp16 out) ==========
#define G1_BM 128
#define G1_BK 16

__device__ __forceinline__ void g1_storeA(uint32_t (*As)[32][4],
                                          const float4* pa, int rr16, int mt, int k0) {
    const float f[8] = {pa[0].x, pa[0].y, pa[0].z, pa[0].w,
                        pa[1].x, pa[1].y, pa[1].z, pa[1].w};
    #pragma unroll
    for (int p = 0; p < 4; p++) {
        const int ke = k0 + 2 * p;
        const __half2 h = __floats2half2_rn(f[2 * p], f[2 * p + 1]);
        const int lane_t = (rr16 & 7) * 4 + ((ke & 7) >> 1);
        const int reg = (rr16 >> 3) + 2 * (ke >> 3);
        As[mt][lane_t][reg] = *(const uint32_t*)&h;
    }
}

__device__ __forceinline__ void g1_storeB(uint32_t (*Bs)[66],
                                          const float4* pb, int bk, int bn16) {
    const int lane_half = (bk & 7) >> 1;
    const int reg = bk >> 3;
    const int hpos = bk & 1;
    #pragma unroll
    for (int i = 0; i < 4; i++) {
        const float f[4] = {pb[i].x, pb[i].y, pb[i].z, pb[i].w};
        #pragma unroll
        for (int e = 0; e < 4; e++) {
            const int n = bn16 + 4 * i + e;
            const int nt = n >> 3, nn = n & 7;
            ((__half*)&Bs[nt][(nn * 4 + lane_half) * 2 + reg])[hpos] = __float2half(f[e]);
        }
    }
}

__global__ __launch_bounds__(256, 1) void gemm1_f16(const float* __restrict__ A,
                                                    const float* __restrict__ B,
                                                    int M) {
    __shared__ __align__(16) uint32_t As[2][8][32][4];   // 8 KB
    __shared__ __align__(16) uint32_t Bs[2][32][66];     // 16.9 KB (padded)

    const int tid  = threadIdx.x;
    const int lane = tid & 31;
    const int warp = tid >> 5;
    const int wm = warp & 1;
    const int wn = warp >> 1;
    const int rowBase = blockIdx.x * G1_BM;

    const int ar = tid >> 1;
    const int ak0 = (tid & 1) * 8;
    const int amt = ar >> 4, arr = ar & 15;
    const int bk = tid >> 4;
    const int bn16 = (tid & 15) * 16;

    float acc[4][8][4];
    #pragma unroll
    for (int mt = 0; mt < 4; mt++)
        #pragma unroll
        for (int nt = 0; nt < 8; nt++)
            #pragma unroll
            for (int r = 0; r < 4; r++) acc[mt][nt][r] = 0.f;

    const int arow = rowBase + ar;
    const float* Arow = A + (size_t)arow * F_IN;
    float4 pa[2], pb[4];

    {
        pa[0] = make_float4(0.f, 0.f, 0.f, 0.f); pa[1] = pa[0];
        if (arow < M) {
            pa[0] = __ldcs((const float4*)(Arow + ak0));
            pa[1] = __ldcs((const float4*)(Arow + ak0 + 4));
        }
        const float* Brow = B + (size_t)bk * F_HID + bn16;
        #pragma unroll
        for (int i = 0; i < 4; i++) pb[i] = *(const float4*)(Brow + 4 * i);
        g1_storeA(As[0], pa, arr, amt, ak0);
        g1_storeB(Bs[0], pb, bk, bn16);
    }
    __syncthreads();

    const int NT = F_IN / G1_BK;   // 32
    for (int t = 0; t < NT; t++) {
        const int buf = t & 1;
        if (t + 1 < NT) {
            const int k0 = (t + 1) * G1_BK;
            pa[0] = make_float4(0.f, 0.f, 0.f, 0.f); pa[1] = pa[0];
            if (arow < M) {
                pa[0] = __ldcs((const float4*)(Arow + k0 + ak0));
                pa[1] = __ldcs((const float4*)(Arow + k0 + ak0 + 4));
            }
            const float* Brow = B + (size_t)(k0 + bk) * F_HID + bn16;
            #pragma unroll
            for (int i = 0; i < 4; i++) pb[i] = *(const float4*)(Brow + 4 * i);
        }

        uint32_t afr[4][4];
        uint32_t bfr[8][2];
        #pragma unroll
        for (int mt = 0; mt < 4; mt++) {
            const uint4 v = *(const uint4*)&As[buf][wm * 4 + mt][lane][0];
            afr[mt][0] = v.x; afr[mt][1] = v.y; afr[mt][2] = v.z; afr[mt][3] = v.w;
        }
        #pragma unroll
        for (int nt = 0; nt < 8; nt++) {
            const uint2 v = *(const uint2*)&Bs[buf][wn * 8 + nt][lane * 2];
            bfr[nt][0] = v.x; bfr[nt][1] = v.y;
        }
        #pragma unroll
        for (int mt = 0; mt < 4; mt++)
            #pragma unroll
            for (int nt = 0; nt < 8; nt++)
                mma_f16(acc[mt][nt], afr[mt], bfr[nt]);

        if (t + 1 < NT) {
            const int nb = buf ^ 1;
            g1_storeA(As[nb], pa, arr, amt, ak0);
            g1_storeB(Bs[nb], pb, bk, bn16);
        }
        __syncthreads();
    }

    #pragma unroll
    for (int mt = 0; mt < 4; mt++) {
        const int row0 = rowBase + wm * 64 + mt * 16 + (lane >> 2);
        #pragma unroll
        for (int nt = 0; nt < 8; nt++) {
            const int col = wn * 64 + nt * 8 + (lane & 3) * 2;
            if (row0 < M)
                *(__half2*)(g_s1h + (size_t)row0 * F_HID + col) =
                    __floats2half2_rn(acc[mt][nt][0], acc[mt][nt][1]);
            if (row0 + 8 < M)
                *(__half2*)(g_s1h + (size_t)(row0 + 8) * F_HID + col) =
                    __floats2half2_rn(acc[mt][nt][2], acc[mt][nt][3]);
        }
    }
}

// ================= CSR build =================================================
__global__ void zero_cnt() {
    const int i = blockIdx.x * blockDim.x + threadIdx.x;
    if (i < N_NODES) g_cnt[i] = 0;
}

__global__ void hist_dst(const int* __restrict__ dst, int E) {
    const int e = blockIdx.x * blockDim.x + threadIdx.x;
    if (e < E) atomicAdd(&g_cnt[__ldcs(dst + e)], 1);
}

__global__ void scan_block() {
    __shared__ int sh[SCAN_B];
    const int t = threadIdx.x;
    const int i = blockIdx.x * SCAN_B + t;
    const int v = (i < N_NODES) ? g_cnt[i] : 0;
    sh[t] = v;
    __syncthreads();
    #pragma unroll
    for (int o = 1; o < SCAN_B; o <<= 1) {
        int x = 0;
        if (t >= o) x = sh[t - o];
        __syncthreads();
        sh[t] += x;
        __syncthreads();
    }
    if (i < N_NODES) g_off[i] = sh[t] - v;
    if (t == SCAN_B - 1) g_blksum[blockIdx.x] = sh[t];
}

__global__ void scan_top() {
    __shared__ int sh[256];
    const int t = threadIdx.x;
    const int v = (t < SCAN_NB) ? g_blksum[t] : 0;
    sh[t] = v;
    __syncthreads();
    #pragma unroll
    for (int o = 1; o < 256; o <<= 1) {
        int x = 0;
        if (t >= o) x = sh[t - o];
        __syncthreads();
        sh[t] += x;
        __syncthreads();
    }
    if (t < SCAN_NB) g_blksum[t] = sh[t] - v;
}

__global__ void scan_add() {
    const int i = blockIdx.x * blockDim.x + threadIdx.x;
    if (i < N_NODES) {
        const int o = g_off[i] + g_blksum[i / SCAN_B];
        g_off[i] = o;
        g_pos[i] = o;
    }
}

__global__ void fill_csr(const int* __restrict__ src, const int* __restrict__ dst,
                         const float* __restrict__ ew, int E) {
    const int e = blockIdx.x * blockDim.x + threadIdx.x;
    if (e < E) {
        const int p = atomicAdd(&g_pos[__ldcs(dst + e)], 1);
        __stcs(&g_csr[p], make_int2(__ldcs(src + e), __float_as_int(__ldcs(ew + e))));
    }
}

// ======== layer-1 gather: warp per node, full 256 feats (fp16 rows) =========
__device__ __forceinline__ void accum8(float* acc, uint4 v, float w) {
    const __half2* h = (const __half2*)&v;
    #pragma unroll
    for (int j = 0; j < 4; j++) {
        const float2 f = __half22float2(h[j]);
        acc[2 * j]     = fmaf(w, f.x, acc[2 * j]);
        acc[2 * j + 1] = fmaf(w, f.y, acc[2 * j + 1]);
    }
}

__global__ __launch_bounds__(256) void gather1(const float* __restrict__ b1) {
    const int n = (blockIdx.x * blockDim.x + threadIdx.x) >> 5;
    const int lane = threadIdx.x & 31;
    if (n >= N_NODES) return;
    const int beg = g_off[n];
    const int end = beg + g_cnt[n];

    float acc[8];
    {
        const float4 blo = __ldg((const float4*)b1 + lane * 2);
        const float4 bhi = __ldg((const float4*)b1 + lane * 2 + 1);
        acc[0] = blo.x; acc[1] = blo.y; acc[2] = blo.z; acc[3] = blo.w;
        acc[4] = bhi.x; acc[5] = bhi.y; acc[6] = bhi.z; acc[7] = bhi.w;
    }

    int e = beg;
    for (; e + 7 < end; e += 8) {
        int2 c[8];
        uint4 v[8];
        #pragma unroll
        for (int i = 0; i < 8; i++) c[i] = __ldcs(&g_csr[e + i]);
        #pragma unroll
        for (int i = 0; i < 8; i++)
            v[i] = __ldg((const uint4*)(g_s1h + (size_t)c[i].x * F_HID) + lane);
        #pragma unroll
        for (int i = 0; i < 8; i++) accum8(acc, v[i], __int_as_float(c[i].y));
    }
    for (; e < end; e++) {
        const int2 c = __ldcs(&g_csr[e]);
        const uint4 v = __ldg((const uint4*)(g_s1h + (size_t)c.x * F_HID) + lane);
        accum8(acc, v, __int_as_float(c.y));
    }

    uint4 o;
    __half2* ph = (__half2*)&o;
    #pragma unroll
    for (int j = 0; j < 4; j++)
        ph[j] = __floats2half2_rn(fmaxf(acc[2 * j], 0.f), fmaxf(acc[2 * j + 1], 0.f));
    __stcs((uint4*)(g_h1h + (size_t)n * F_HID) + lane, o);
}

// ====== gemm2: support2 = a1 @ W2 (fp16 mma; N=40 = 5 n-tiles exactly) ======
#define G2_NT 5
__global__ __launch_bounds__(256) void gemm2_mma(const float* __restrict__ W2) {
    __shared__ uint32_t Wf[16][G2_NT][32][2];   // 20 KB: B fragments per (ktile, ntile)

    const int tid = threadIdx.x;
    // pack W2 (fp32 [256,40]) into fp16 mma B-fragments
    for (int idx = tid; idx < 16 * G2_NT * 32; idx += 256) {
        const int kt = idx / (G2_NT * 32);
        const int rem = idx % (G2_NT * 32);
        const int nt = rem / 32;
        const int ln = rem % 32;
        const int n = nt * 8 + (ln >> 2);
        const int k0 = kt * 16 + (ln & 3) * 2;
        const __half2 h0 = __floats2half2_rn(W2[(size_t)k0 * F_OUT + n],
                                             W2[(size_t)(k0 + 1) * F_OUT + n]);
        const __half2 h1 = __floats2half2_rn(W2[(size_t)(k0 + 8) * F_OUT + n],
                                             W2[(size_t)(k0 + 9) * F_OUT + n]);
        Wf[kt][nt][ln][0] = *(const uint32_t*)&h0;
        Wf[kt][nt][ln][1] = *(const uint32_t*)&h1;
    }
    __syncthreads();

    const int lane = tid & 31, warp = tid >> 5;
    const int node0 = blockIdx.x * 128 + warp * 16 + (lane >> 2);
    const int node1 = node0 + 8;
    const bool v0 = node0 < N_NODES, v1 = node1 < N_NODES;

    float acc[G2_NT][4];
    #pragma unroll
    for (int nt = 0; nt < G2_NT; nt++)
        #pragma unroll
        for (int r = 0; r < 4; r++) acc[nt][r] = 0.f;

    const __half* r0 = g_h1h + (size_t)node0 * F_HID;
    const __half* r1 = g_h1h + (size_t)node1 * F_HID;

    #pragma unroll
    for (int kt = 0; kt < 16; kt++) {
        const int kof = kt * 16 + (lane & 3) * 2;
        uint32_t a[4];
        a[0] = v0 ? __ldg((const uint32_t*)(r0 + kof))     : 0u;
        a[1] = v1 ? __ldg((const uint32_t*)(r1 + kof))     : 0u;
        a[2] = v0 ? __ldg((const uint32_t*)(r0 + kof + 8)) : 0u;
        a[3] = v1 ? __ldg((const uint32_t*)(r1 + kof + 8)) : 0u;
        #pragma unroll
        for (int nt = 0; nt < G2_NT; nt++) {
            const uint32_t b[2] = {Wf[kt][nt][lane][0], Wf[kt][nt][lane][1]};
            mma_f16(acc[nt], a, b);
        }
    }

    const int col = (lane & 3) * 2;
    #pragma unroll
    for (int nt = 0; nt < G2_NT; nt++) {
        if (v0)
            *(__half2*)(g_s2h + (size_t)node0 * F_OUT + nt * 8 + col) =
                __floats2half2_rn(acc[nt][0], acc[nt][1]);
        if (v1)
            *(__half2*)(g_s2h + (size_t)node1 * F_OUT + nt * 8 + col) =
                __floats2half2_rn(acc[nt][2], acc[nt][3]);
    }
}

// ========== layer-2 gather fused with log_softmax: warp per node ============
__global__ __launch_bounds__(256) void gather2_softmax(const float* __restrict__ b2,
                                                       float* __restrict__ out) {
    const int n = (blockIdx.x * blockDim.x + threadIdx.x) >> 5;
    const int lane = threadIdx.x & 31;
    if (n >= N_NODES) return;
    const int beg = g_off[n];
    const int end = beg + g_cnt[n];
    const bool act = lane < (F_OUT / 2);

    float accA = 0.f, accB = 0.f;
    if (act) {
        const float2 b = __ldg((const float2*)b2 + lane);
        accA = b.x; accB = b.y;
    }

    int e = beg;
    for (; e + 1 < end; e += 2) {
        const int2 c0 = __ldcs(&g_csr[e]);
        const int2 c1 = __ldcs(&g_csr[e + 1]);
        if (act) {
            const __half2 v0 = __ldg((const __half2*)(g_s2h + (size_t)c0.x * F_OUT) + lane);
            const __half2 v1 = __ldg((const __half2*)(g_s2h + (size_t)c1.x * F_OUT) + lane);
            const float w0 = __int_as_float(c0.y);
            const float w1 = __int_as_float(c1.y);
            const float2 f0 = __half22float2(v0);
            const float2 f1 = __half22float2(v1);
            accA = fmaf(w0, f0.x, accA); accB = fmaf(w0, f0.y, accB);
            accA = fmaf(w1, f1.x, accA); accB = fmaf(w1, f1.y, accB);
        }
    }
    if (e < end) {
        const int2 c = __ldcs(&g_csr[e]);
        if (act) {
            const __half2 v = __ldg((const __half2*)(g_s2h + (size_t)c.x * F_OUT) + lane);
            const float w = __int_as_float(c.y);
            const float2 f = __half22float2(v);
            accA = fmaf(w, f.x, accA); accB = fmaf(w, f.y, accB);
        }
    }

    const float NEG_INF = __int_as_float(0xff800000);
    float m = act ? fmaxf(accA, accB) : NEG_INF;
    #pragma unroll
    for (int o = 16; o > 0; o >>= 1)
        m = fmaxf(m, __shfl_xor_sync(0xffffffffu, m, o));
    float s = act ? (expf(accA - m) + expf(accB - m)) : 0.f;
    #pragma unroll
    for (int o = 16; o > 0; o >>= 1)
        s += __shfl_xor_sync(0xffffffffu, s, o);
    const float l = m + logf(s);

    if (act)
        *((float2*)(out + (size_t)n * F_OUT) + lane) = make_float2(accA - l, accB - l);
}

// ---------------- launch ----------------------------------------------------
extern "C" void kernel_launch(void* const* d_in, const int* in_sizes, int n_in,
                              void* d_out, int out_size) {
    const float* x   = (const float*)d_in[0];
    const int*   ei  = (const int*)d_in[1];
    const float* ew  = (const float*)d_in[2];
    const float* W1  = (const float*)d_in[3];
    const float* b1  = (const float*)d_in[4];
    const float* W2  = (const float*)d_in[5];
    const float* b2  = (const float*)d_in[6];
    float* out = (float*)d_out;

    const int E = in_sizes[2];
    const int* src = ei;
    const int* dst = ei + E;

    // Fork: CSR build runs concurrently with gemm1 (independent data).
    cudaStream_t s2;
    cudaStreamCreate(&s2);
    cudaEvent_t evFork, evJoin;
    cudaEventCreateWithFlags(&evFork, cudaEventDisableTiming);
    cudaEventCreateWithFlags(&evJoin, cudaEventDisableTiming);

    cudaEventRecord(evFork, 0);
    cudaStreamWaitEvent(s2, evFork, 0);

    // branch A (main stream): support1 = x @ W1
    gemm1_f16<<<(N_NODES + G1_BM - 1) / G1_BM, 256>>>(x, W1, N_NODES);

    // branch B (side stream): CSR build (dst-bucketed)
    {
        const int nb = (N_NODES + 255) / 256;
        const int eb = (E + 255) / 256;
        zero_cnt<<<nb, 256, 0, s2>>>();
        hist_dst<<<eb, 256, 0, s2>>>(dst, E);
        scan_block<<<SCAN_NB, SCAN_B, 0, s2>>>();
        scan_top<<<1, 256, 0, s2>>>();
        scan_add<<<nb, 256, 0, s2>>>();
        fill_csr<<<eb, 256, 0, s2>>>(src, dst, ew, E);
    }

    cudaEventRecord(evJoin, s2);
    cudaStreamWaitEvent(0, evJoin, 0);

    // layer-1 gather (needs both branches) + relu + fp16 store
    gather1<<<(N_NODES * 32 + 255) / 256, 256>>>(b1);
    // support2 = a1 @ W2  (fp16 mma)
    gemm2_mma<<<(N_NODES + 127) / 128, 256>>>(W2);
    // out = log_softmax(b2 + gather(ew * support2[src]))
    gather2_softmax<<<(N_NODES * 32 + 255) / 256, 256>>>(b2, out);

    cudaStreamDestroy(s2);
    cudaEventDestroy(evFork);
    cudaEventDestroy(evJoin);
}

// round 8
// speedup vs baseline: 4.3893x; 1.1544x over previous
#include <cuda_runtime.h>
#include <cuda_fp16.h>
#include <cstdint>

#define N_NODES 100000
#define F_IN    512
#define F_HID   256
#define F_OUT   40
#define E_MAX   3200000

#define SCAN_B  512
#define SCAN_NB ((N_NODES + SCAN_B - 1) / SCAN_B)   // 196

// ---------------- scratch (device globals; no allocation allowed) ----------
__device__ __align__(128) __half g_s1h[(size_t)N_NODES * F_HID];   // 51.2 MB
__device__ __align__(128) __half g_h1h[(size_t)N_NODES * F_HID];   // 51.2 MB
__device__ __align__(128) __half g_s2h[(size_t)N_NODES * F_OUT];   // 8 MB

// W1 pre-packed into mma B-fragment order: [kt(32)][nt(32)][lane(32)][2]
__device__ __align__(16) uint32_t g_w1f[32 * 32 * 32 * 2];          // 256 KB

__device__ int  g_cnt[N_NODES];
__device__ int  g_off[N_NODES];
__device__ int  g_pos[N_NODES];
__device__ int  g_blksum[SCAN_NB];
__device__ __align__(16) int2 g_csr[E_MAX];    // (src, float-bits of w)

// ---------------- fp16 mma helper -------------------------------------------
__device__ __forceinline__ void mma_f16(float* c, const uint32_t* a, const uint32_t* b) {
    asm volatile("mma.sync.aligned.m16n8k16.row.col.f32.f16.f16.f32 "
                 "{%0,%1,%2,%3}, {%4,%5,%6,%7}, {%8,%9}, {%0,%1,%2,%3};"
                 : "+f"(c[0]), "+f"(c[1]), "+f"(c[2]), "+f"(c[3])
                 : "r"(a[0]), "r"(a[1]), "r"(a[2]), "r"(a[3]),
                   "r"(b[0]), "r"(b[1]));
}

// ================ pack W1 (fp32 [512,256]) into fragment order ===============
__global__ void pack_W1(const float* __restrict__ W1) {
    const int idx = blockIdx.x * blockDim.x + threadIdx.x;   // 0..32767
    if (idx >= 32 * 32 * 32) return;
    const int kt = idx >> 10;
    const int rem = idx & 1023;
    const int nt = rem >> 5;
    const int ln = rem & 31;
    const int n = nt * 8 + (ln >> 2);
    const int k = kt * 16 + (ln & 3) * 2;
    const __half2 h0 = __floats2half2_rn(W1[(size_t)k * F_HID + n],
                                         W1[(size_t)(k + 1) * F_HID + n]);
    const __half2 h1 = __floats2half2_rn(W1[(size_t)(k + 8) * F_HID + n],
                                         W1[(size_t)(k + 9) * F_HID + n]);
    g_w1f[idx * 2]     = *(const uint32_t*)&h0;
    g_w1f[idx * 2 + 1] = *(const uint32_t*)&h1;
}

// ================= gemm1: support1 = x @ W1  (fp16 MMA, fp16 out) ==========
// Block 128(M) x 256(N) x 32(K); 8 warps, warp tile 64x64.
// A in smem ([mt][reg][lane] fragment order, STS.128 fills);
// B fragments read directly from pre-packed g_w1f (L2/L1 resident).
#define G1_BM 128
#define G1_BK 32
#define AS_PAD 36   // words per lane-row (16B-aligned, bank-skewed)

__global__ __launch_bounds__(256, 1) void gemm1_f16(const float* __restrict__ A, int M) {
    __shared__ __align__(16) uint32_t As[2][8][8][AS_PAD];   // 18.4 KB

    const int tid  = threadIdx.x;
    const int lane = tid & 31;
    const int warp = tid >> 5;
    const int wm = warp & 1;
    const int wn = warp >> 1;
    const int rowBase = blockIdx.x * G1_BM;

    const int ar  = tid >> 1;           // row 0..127
    const int aks = tid & 1;            // k16-step within tile
    const int amt = ar >> 4, arr = ar & 15;
    const int b0  = arr >> 3;           // base reg (0 or 1)
    const int l0  = (arr & 7) * 4;

    float acc[4][8][4];
    #pragma unroll
    for (int mt = 0; mt < 4; mt++)
        #pragma unroll
        for (int nt = 0; nt < 8; nt++)
            #pragma unroll
            for (int r = 0; r < 4; r++) acc[mt][nt][r] = 0.f;

    const int arow = rowBase + ar;
    const float* Arow = A + (size_t)arow * F_IN + aks * 16;
    float4 pa[4];

    // prologue: load + store tile 0
    {
        #pragma unroll
        for (int j = 0; j < 4; j++)
            pa[j] = (arow < M) ? __ldcs((const float4*)(Arow + 4 * j))
                               : make_float4(0.f, 0.f, 0.f, 0.f);
        const float* f = (const float*)pa;
        uint4 lo, hi;
        uint32_t* plo = (uint32_t*)&lo;
        uint32_t* phi = (uint32_t*)&hi;
        #pragma unroll
        for (int p = 0; p < 4; p++) {
            const __half2 a = __floats2half2_rn(f[2 * p],     f[2 * p + 1]);
            const __half2 b = __floats2half2_rn(f[8 + 2 * p], f[9 + 2 * p]);
            plo[p] = *(const uint32_t*)&a;
            phi[p] = *(const uint32_t*)&b;
        }
        *(uint4*)&As[0][amt][aks * 4 + b0][l0]     = lo;
        *(uint4*)&As[0][amt][aks * 4 + b0 + 2][l0] = hi;
    }
    __syncthreads();

    const int NT = F_IN / G1_BK;   // 16
    for (int t = 0; t < NT; t++) {
        const int buf = t & 1;
        // prefetch next tile's A
        if (t + 1 < NT) {
            const float* Anext = Arow + (t + 1) * G1_BK;
            #pragma unroll
            for (int j = 0; j < 4; j++)
                pa[j] = (arow < M) ? __ldcs((const float4*)(Anext + 4 * j))
                                   : make_float4(0.f, 0.f, 0.f, 0.f);
        }

        #pragma unroll
        for (int ks = 0; ks < 2; ks++) {
            const int kt = t * 2 + ks;
            // B fragments straight from packed gmem
            uint32_t bfr[8][2];
            #pragma unroll
            for (int nt = 0; nt < 8; nt++) {
                const uint2 v = __ldg((const uint2*)
                    &g_w1f[(((size_t)kt * 32 + wn * 8 + nt) * 32 + lane) * 2]);
                bfr[nt][0] = v.x; bfr[nt][1] = v.y;
            }
            // A fragments from smem
            uint32_t afr[4][4];
            #pragma unroll
            for (int mt = 0; mt < 4; mt++)
                #pragma unroll
                for (int r = 0; r < 4; r++)
                    afr[mt][r] = As[buf][wm * 4 + mt][ks * 4 + r][lane];
            #pragma unroll
            for (int mt = 0; mt < 4; mt++)
                #pragma unroll
                for (int nt = 0; nt < 8; nt++)
                    mma_f16(acc[mt][nt], afr[mt], bfr[nt]);
        }

        if (t + 1 < NT) {
            const int nb = buf ^ 1;
            const float* f = (const float*)pa;
            uint4 lo, hi;
            uint32_t* plo = (uint32_t*)&lo;
            uint32_t* phi = (uint32_t*)&hi;
            #pragma unroll
            for (int p = 0; p < 4; p++) {
                const __half2 a = __floats2half2_rn(f[2 * p],     f[2 * p + 1]);
                const __half2 b = __floats2half2_rn(f[8 + 2 * p], f[9 + 2 * p]);
                plo[p] = *(const uint32_t*)&a;
                phi[p] = *(const uint32_t*)&b;
            }
            *(uint4*)&As[nb][amt][aks * 4 + b0][l0]     = lo;
            *(uint4*)&As[nb][amt][aks * 4 + b0 + 2][l0] = hi;
        }
        __syncthreads();
    }

    // epilogue: fp16 store
    #pragma unroll
    for (int mt = 0; mt < 4; mt++) {
        const int row0 = rowBase + wm * 64 + mt * 16 + (lane >> 2);
        #pragma unroll
        for (int nt = 0; nt < 8; nt++) {
            const int col = wn * 64 + nt * 8 + (lane & 3) * 2;
            if (row0 < M)
                *(__half2*)(g_s1h + (size_t)row0 * F_HID + col) =
                    __floats2half2_rn(acc[mt][nt][0], acc[mt][nt][1]);
            if (row0 + 8 < M)
                *(__half2*)(g_s1h + (size_t)(row0 + 8) * F_HID + col) =
                    __floats2half2_rn(acc[mt][nt][2], acc[mt][nt][3]);
        }
    }
}

// ================= CSR build =================================================
__global__ void zero_cnt() {
    const int i = blockIdx.x * blockDim.x + threadIdx.x;
    if (i < N_NODES) g_cnt[i] = 0;
}

__global__ void hist_dst(const int* __restrict__ dst, int E) {
    const int e = blockIdx.x * blockDim.x + threadIdx.x;
    if (e < E) atomicAdd(&g_cnt[__ldcs(dst + e)], 1);
}

__global__ void scan_block() {
    __shared__ int sh[SCAN_B];
    const int t = threadIdx.x;
    const int i = blockIdx.x * SCAN_B + t;
    const int v = (i < N_NODES) ? g_cnt[i] : 0;
    sh[t] = v;
    __syncthreads();
    #pragma unroll
    for (int o = 1; o < SCAN_B; o <<= 1) {
        int x = 0;
        if (t >= o) x = sh[t - o];
        __syncthreads();
        sh[t] += x;
        __syncthreads();
    }
    if (i < N_NODES) g_off[i] = sh[t] - v;
    if (t == SCAN_B - 1) g_blksum[blockIdx.x] = sh[t];
}

__global__ void scan_top() {
    __shared__ int sh[256];
    const int t = threadIdx.x;
    const int v = (t < SCAN_NB) ? g_blksum[t] : 0;
    sh[t] = v;
    __syncthreads();
    #pragma unroll
    for (int o = 1; o < 256; o <<= 1) {
        int x = 0;
        if (t >= o) x = sh[t - o];
        __syncthreads();
        sh[t] += x;
        __syncthreads();
    }
    if (t < SCAN_NB) g_blksum[t] = sh[t] - v;
}

__global__ void scan_add() {
    const int i = blockIdx.x * blockDim.x + threadIdx.x;
    if (i < N_NODES) {
        const int o = g_off[i] + g_blksum[i / SCAN_B];
        g_off[i] = o;
        g_pos[i] = o;
    }
}

__global__ void fill_csr(const int* __restrict__ src, const int* __restrict__ dst,
                         const float* __restrict__ ew, int E) {
    const int e = blockIdx.x * blockDim.x + threadIdx.x;
    if (e < E) {
        const int p = atomicAdd(&g_pos[__ldcs(dst + e)], 1);
        __stcs(&g_csr[p], make_int2(__ldcs(src + e), __float_as_int(__ldcs(ew + e))));
    }
}

// ======== layer-1 gather: warp per node, full 256 feats (fp16 rows) =========
__device__ __forceinline__ void accum8(float* acc, uint4 v, float w) {
    const __half2* h = (const __half2*)&v;
    #pragma unroll
    for (int j = 0; j < 4; j++) {
        const float2 f = __half22float2(h[j]);
        acc[2 * j]     = fmaf(w, f.x, acc[2 * j]);
        acc[2 * j + 1] = fmaf(w, f.y, acc[2 * j + 1]);
    }
}

__global__ __launch_bounds__(256) void gather1(const float* __restrict__ b1) {
    const int n = (blockIdx.x * blockDim.x + threadIdx.x) >> 5;
    const int lane = threadIdx.x & 31;
    if (n >= N_NODES) return;
    const int beg = g_off[n];
    const int end = beg + g_cnt[n];

    float acc[8];
    {
        const float4 blo = __ldg((const float4*)b1 + lane * 2);
        const float4 bhi = __ldg((const float4*)b1 + lane * 2 + 1);
        acc[0] = blo.x; acc[1] = blo.y; acc[2] = blo.z; acc[3] = blo.w;
        acc[4] = bhi.x; acc[5] = bhi.y; acc[6] = bhi.z; acc[7] = bhi.w;
    }

    int e = beg;
    for (; e + 7 < end; e += 8) {
        int2 c[8];
        uint4 v[8];
        #pragma unroll
        for (int i = 0; i < 8; i++) c[i] = __ldcs(&g_csr[e + i]);
        #pragma unroll
        for (int i = 0; i < 8; i++)
            v[i] = __ldg((const uint4*)(g_s1h + (size_t)c[i].x * F_HID) + lane);
        #pragma unroll
        for (int i = 0; i < 8; i++) accum8(acc, v[i], __int_as_float(c[i].y));
    }
    for (; e < end; e++) {
        const int2 c = __ldcs(&g_csr[e]);
        const uint4 v = __ldg((const uint4*)(g_s1h + (size_t)c.x * F_HID) + lane);
        accum8(acc, v, __int_as_float(c.y));
    }

    uint4 o;
    __half2* ph = (__half2*)&o;
    #pragma unroll
    for (int j = 0; j < 4; j++)
        ph[j] = __floats2half2_rn(fmaxf(acc[2 * j], 0.f), fmaxf(acc[2 * j + 1], 0.f));
    __stcs((uint4*)(g_h1h + (size_t)n * F_HID) + lane, o);
}

// ====== gemm2: support2 = a1 @ W2 (fp16 mma; N=40 = 5 n-tiles exactly) ======
#define G2_NT 5
__global__ __launch_bounds__(256) void gemm2_mma(const float* __restrict__ W2) {
    __shared__ uint32_t Wf[16][G2_NT][32][2];   // 20 KB

    const int tid = threadIdx.x;
    for (int idx = tid; idx < 16 * G2_NT * 32; idx += 256) {
        const int kt = idx / (G2_NT * 32);
        const int rem = idx % (G2_NT * 32);
        const int nt = rem / 32;
        const int ln = rem % 32;
        const int n = nt * 8 + (ln >> 2);
        const int k0 = kt * 16 + (ln & 3) * 2;
        const __half2 h0 = __floats2half2_rn(W2[(size_t)k0 * F_OUT + n],
                                             W2[(size_t)(k0 + 1) * F_OUT + n]);
        const __half2 h1 = __floats2half2_rn(W2[(size_t)(k0 + 8) * F_OUT + n],
                                             W2[(size_t)(k0 + 9) * F_OUT + n]);
        Wf[kt][nt][ln][0] = *(const uint32_t*)&h0;
        Wf[kt][nt][ln][1] = *(const uint32_t*)&h1;
    }
    __syncthreads();

    const int lane = tid & 31, warp = tid >> 5;
    const int node0 = blockIdx.x * 128 + warp * 16 + (lane >> 2);
    const int node1 = node0 + 8;
    const bool v0 = node0 < N_NODES, v1 = node1 < N_NODES;

    float acc[G2_NT][4];
    #pragma unroll
    for (int nt = 0; nt < G2_NT; nt++)
        #pragma unroll
        for (int r = 0; r < 4; r++) acc[nt][r] = 0.f;

    const __half* r0 = g_h1h + (size_t)node0 * F_HID;
    const __half* r1 = g_h1h + (size_t)node1 * F_HID;

    #pragma unroll
    for (int kt = 0; kt < 16; kt++) {
        const int kof = kt * 16 + (lane & 3) * 2;
        uint32_t a[4];
        a[0] = v0 ? __ldg((const uint32_t*)(r0 + kof))     : 0u;
        a[1] = v1 ? __ldg((const uint32_t*)(r1 + kof))     : 0u;
        a[2] = v0 ? __ldg((const uint32_t*)(r0 + kof + 8)) : 0u;
        a[3] = v1 ? __ldg((const uint32_t*)(r1 + kof + 8)) : 0u;
        #pragma unroll
        for (int nt = 0; nt < G2_NT; nt++) {
            const uint32_t b[2] = {Wf[kt][nt][lane][0], Wf[kt][nt][lane][1]};
            mma_f16(acc[nt], a, b);
        }
    }

    const int col = (lane & 3) * 2;
    #pragma unroll
    for (int nt = 0; nt < G2_NT; nt++) {
        if (v0)
            *(__half2*)(g_s2h + (size_t)node0 * F_OUT + nt * 8 + col) =
                __floats2half2_rn(acc[nt][0], acc[nt][1]);
        if (v1)
            *(__half2*)(g_s2h + (size_t)node1 * F_OUT + nt * 8 + col) =
                __floats2half2_rn(acc[nt][2], acc[nt][3]);
    }
}

// ========== layer-2 gather fused with log_softmax: warp per node ============
__global__ __launch_bounds__(256) void gather2_softmax(const float* __restrict__ b2,
                                                       float* __restrict__ out) {
    const int n = (blockIdx.x * blockDim.x + threadIdx.x) >> 5;
    const int lane = threadIdx.x & 31;
    if (n >= N_NODES) return;
    const int beg = g_off[n];
    const int end = beg + g_cnt[n];
    const bool act = lane < (F_OUT / 2);

    float accA = 0.f, accB = 0.f;
    if (act) {
        const float2 b = __ldg((const float2*)b2 + lane);
        accA = b.x; accB = b.y;
    }

    int e = beg;
    for (; e + 1 < end; e += 2) {
        const int2 c0 = __ldcs(&g_csr[e]);
        const int2 c1 = __ldcs(&g_csr[e + 1]);
        if (act) {
            const __half2 v0 = __ldg((const __half2*)(g_s2h + (size_t)c0.x * F_OUT) + lane);
            const __half2 v1 = __ldg((const __half2*)(g_s2h + (size_t)c1.x * F_OUT) + lane);
            const float w0 = __int_as_float(c0.y);
            const float w1 = __int_as_float(c1.y);
            const float2 f0 = __half22float2(v0);
            const float2 f1 = __half22float2(v1);
            accA = fmaf(w0, f0.x, accA); accB = fmaf(w0, f0.y, accB);
            accA = fmaf(w1, f1.x, accA); accB = fmaf(w1, f1.y, accB);
        }
    }
    if (e < end) {
        const int2 c = __ldcs(&g_csr[e]);
        if (act) {
            const __half2 v = __ldg((const __half2*)(g_s2h + (size_t)c.x * F_OUT) + lane);
            const float w = __int_as_float(c.y);
            const float2 f = __half22float2(v);
            accA = fmaf(w, f.x, accA); accB = fmaf(w, f.y, accB);
        }
    }

    const float NEG_INF = __int_as_float(0xff800000);
    float m = act ? fmaxf(accA, accB) : NEG_INF;
    #pragma unroll
    for (int o = 16; o > 0; o >>= 1)
        m = fmaxf(m, __shfl_xor_sync(0xffffffffu, m, o));
    float s = act ? (expf(accA - m) + expf(accB - m)) : 0.f;
    #pragma unroll
    for (int o = 16; o > 0; o >>= 1)
        s += __shfl_xor_sync(0xffffffffu, s, o);
    const float l = m + logf(s);

    if (act)
        *((float2*)(out + (size_t)n * F_OUT) + lane) = make_float2(accA - l, accB - l);
}

// ---------------- launch ----------------------------------------------------
extern "C" void kernel_launch(void* const* d_in, const int* in_sizes, int n_in,
                              void* d_out, int out_size) {
    const float* x   = (const float*)d_in[0];
    const int*   ei  = (const int*)d_in[1];
    const float* ew  = (const float*)d_in[2];
    const float* W1  = (const float*)d_in[3];
    const float* b1  = (const float*)d_in[4];
    const float* W2  = (const float*)d_in[5];
    const float* b2  = (const float*)d_in[6];
    float* out = (float*)d_out;

    const int E = in_sizes[2];
    const int* src = ei;
    const int* dst = ei + E;

    // Fork: CSR build runs concurrently with W1 pack + gemm1.
    cudaStream_t s2;
    cudaStreamCreate(&s2);
    cudaEvent_t evFork, evJoin;
    cudaEventCreateWithFlags(&evFork, cudaEventDisableTiming);
    cudaEventCreateWithFlags(&evJoin, cudaEventDisableTiming);

    cudaEventRecord(evFork, 0);
    cudaStreamWaitEvent(s2, evFork, 0);

    // branch A (main stream): pack W1, then support1 = x @ W1
    pack_W1<<<128, 256>>>(W1);
    gemm1_f16<<<(N_NODES + G1_BM - 1) / G1_BM, 256>>>(x, N_NODES);

    // branch B (side stream): CSR build (dst-bucketed)
    {
        const int nb = (N_NODES + 255) / 256;
        const int eb = (E + 255) / 256;
        zero_cnt<<<nb, 256, 0, s2>>>();
        hist_dst<<<eb, 256, 0, s2>>>(dst, E);
        scan_block<<<SCAN_NB, SCAN_B, 0, s2>>>();
        scan_top<<<1, 256, 0, s2>>>();
        scan_add<<<nb, 256, 0, s2>>>();
        fill_csr<<<eb, 256, 0, s2>>>(src, dst, ew, E);
    }

    cudaEventRecord(evJoin, s2);
    cudaStreamWaitEvent(0, evJoin, 0);

    // layer-1 gather + relu + fp16 store
    gather1<<<(N_NODES * 32 + 255) / 256, 256>>>(b1);
    // support2 = a1 @ W2  (fp16 mma)
    gemm2_mma<<<(N_NODES + 127) / 128, 256>>>(W2);
    // out = log_softmax(b2 + gather(ew * support2[src]))
    gather2_softmax<<<(N_NODES * 32 + 255) / 256, 256>>>(b2, out);

    cudaStreamDestroy(s2);
    cudaEventDestroy(evFork);
    cudaEventDestroy(evJoin);
}